// round 1
// baseline (speedup 1.0000x reference)
#include <cuda_runtime.h>
#include <math.h>

#define BB 8
#define NA 2000
#define DD 256
#define EE 64000
#define KNUM 2196
#define KP 2208          /* 16 * 138, padded with G=0 */
#define PI_F 3.14159265358979f
#define C_SELF (-0.7978845608028654f)   /* -sqrt(2/pi)/sigma */

/* ---------------- scratch (device globals; no allocations allowed) -------- */
__device__ float g_q  [BB*NA*DD];            /* charges                 16.4MB */
__device__ float g_pot[BB*NA*DD];            /* real+recip accumulation 16.4MB */
__device__ float g_cos[(size_t)BB*NA*KP];    /* cos(ph)  141MB */
__device__ float g_sin[(size_t)BB*NA*KP];    /* sin(ph)  141MB */
__device__ float g_Sc [BB*KP*DD];            /* G * (c^T q) */
__device__ float g_Ss [BB*KP*DD];            /* G * (s^T q) */
__device__ float g_G  [BB*KP];
__device__ float g_kv [BB*KP*3];

/* ---------------- k-vectors + Green's function ---------------------------- */
__global__ void k_kG(const float* __restrict__ cell) {
    int k = blockIdx.x * blockDim.x + threadIdx.x;
    int b = blockIdx.y;
    if (k >= KP) return;
    const float* C = cell + b * 9;
    float c00=C[0],c01=C[1],c02=C[2];
    float c10=C[3],c11=C[4],c12=C[5];
    float c20=C[6],c21=C[7],c22=C[8];
    float det = c00*(c11*c22-c12*c21) - c01*(c10*c22-c12*c20) + c02*(c10*c21-c11*c20);
    float id = 1.0f/det;
    float i00=(c11*c22-c12*c21)*id, i01=(c02*c21-c01*c22)*id, i02=(c01*c12-c02*c11)*id;
    float i10=(c12*c20-c10*c22)*id, i11=(c00*c22-c02*c20)*id, i12=(c02*c10-c00*c12)*id;
    float i20=(c10*c21-c11*c20)*id, i21=(c01*c20-c00*c21)*id, i22=(c00*c11-c01*c10)*id;
    float kx=0.f, ky=0.f, kz=0.f, G=0.f;
    if (k < KNUM) {
        int m = k + (k >= 1098);               /* skip the (0,0,0) row */
        float ni = (float)(m/169 - 6);
        float nj = (float)((m/13)%13 - 6);
        float nk = (float)(m%13 - 6);
        kx = 2.0f*PI_F*(i00*ni + i01*nj + i02*nk);
        ky = 2.0f*PI_F*(i10*ni + i11*nj + i12*nk);
        kz = 2.0f*PI_F*(i20*ni + i21*nj + i22*nk);
        float k2 = kx*kx + ky*ky + kz*kz;
        G = 4.0f*PI_F/fabsf(det) * __expf(-0.5f*k2) / k2;   /* sigma = 1 */
    }
    g_kv[(b*KP + k)*3 + 0] = kx;
    g_kv[(b*KP + k)*3 + 1] = ky;
    g_kv[(b*KP + k)*3 + 2] = kz;
    g_G [ b*KP + k]        = G;
}

/* ---------------- charges = features @ W^T + b (NT SGEMM) ----------------- */
__global__ void k_charges(const float* __restrict__ A, const float* __restrict__ Wm,
                          const float* __restrict__ bias) {
    __shared__ float As[64][17];
    __shared__ float Bs[64][17];
    int m0 = blockIdx.x * 64, n0 = blockIdx.y * 64;
    int tid = threadIdx.x, tx = tid & 15, ty = tid >> 4;
    float acc[4][4] = {};
    for (int kt = 0; kt < 256; kt += 16) {
        #pragma unroll
        for (int l = tid; l < 1024; l += 256) {
            int kk = l & 15, mm = l >> 4;
            As[mm][kk] = A [(m0+mm)*256 + kt + kk];
            Bs[mm][kk] = Wm[(n0+mm)*256 + kt + kk];
        }
        __syncthreads();
        #pragma unroll
        for (int kk = 0; kk < 16; kk++) {
            float a[4], bv[4];
            #pragma unroll
            for (int i = 0; i < 4; i++) { a[i]  = As[ty*4+i][kk]; bv[i] = Bs[tx*4+i][kk]; }
            #pragma unroll
            for (int i = 0; i < 4; i++)
                #pragma unroll
                for (int j = 0; j < 4; j++) acc[i][j] += a[i] * bv[j];
        }
        __syncthreads();
    }
    #pragma unroll
    for (int i = 0; i < 4; i++)
        #pragma unroll
        for (int j = 0; j < 4; j++)
            g_q[(m0+ty*4+i)*256 + n0+tx*4+j] = acc[i][j] + bias[n0+tx*4+j];
}

/* ---------------- pot = 0 ------------------------------------------------- */
__global__ void k_zero() {
    int idx = blockIdx.x * blockDim.x + threadIdx.x;
    g_pot[idx] = 0.0f;
}

/* ---------------- phases: cos/sin(pos . kvec) ----------------------------- */
__global__ void k_phase(const float* __restrict__ pos) {
    int bn = blockIdx.x;
    int b  = bn / NA;
    float x = pos[bn*3+0], y = pos[bn*3+1], z = pos[bn*3+2];
    const float* kv = g_kv + b * KP * 3;
    size_t base = (size_t)bn * KP;
    for (int k = threadIdx.x; k < KP; k += 256) {
        float c = 0.f, s = 0.f;
        if (k < KNUM) {
            float ph = x*kv[k*3] + y*kv[k*3+1] + z*kv[k*3+2];
            __sincosf(ph, &s, &c);
        }
        g_cos[base + k] = c;
        g_sin[base + k] = s;
    }
}

/* ---------------- real-space scatter: warp per edge ----------------------- */
__global__ void k_edges(const int* __restrict__ nbidx, const float* __restrict__ nbdist) {
    int w = (blockIdx.x * blockDim.x + threadIdx.x) >> 5;
    int lane = threadIdx.x & 31;
    if (w >= BB*EE) return;
    int b = w / EE;
    int i = nbidx[w*2 + 0];
    int j = nbidx[w*2 + 1];
    float d = nbdist[w];
    float v  = erfcf(d * 0.70710678118f) / d;
    float fc = (d < 5.0f) ? 0.5f*(__cosf(PI_F * d * 0.2f) + 1.0f) : 0.0f;
    float vsr = v - fc / d;
    const float* qj = g_q   + (b*NA + j) * DD;
    float*       pi = g_pot + (b*NA + i) * DD;
    #pragma unroll
    for (int t = 0; t < 8; t++) {
        int dch = t*32 + lane;
        atomicAdd(pi + dch, vsr * __ldg(qj + dch));
    }
}

/* ---------------- TN fused: Sc = G*(c^T q), Ss = G*(s^T q) ---------------- */
__global__ void k_sf() {
    __shared__ float sc[16][64];
    __shared__ float ss[16][64];
    __shared__ float sq[16][64];
    int b  = blockIdx.z;
    int m0 = blockIdx.x * 64;   /* k-vector tile */
    int n0 = blockIdx.y * 64;   /* channel tile  */
    int tid = threadIdx.x, tx = tid & 15, ty = tid >> 4;
    const float* cosb = g_cos + (size_t)b * NA * KP;
    const float* sinb = g_sin + (size_t)b * NA * KP;
    const float* qb   = g_q   + b * NA * DD;
    float accC[4][4] = {}, accS[4][4] = {};
    for (int nt = 0; nt < NA; nt += 16) {
        #pragma unroll
        for (int l = tid; l < 1024; l += 256) {
            int mm = l & 63, kk = l >> 6;
            int gm = m0 + mm;
            float vc = 0.f, vs = 0.f;
            if (gm < KP) {
                size_t off = (size_t)(nt+kk) * KP + gm;
                vc = cosb[off]; vs = sinb[off];
            }
            sc[kk][mm] = vc;
            ss[kk][mm] = vs;
            sq[kk][mm] = qb[(nt+kk)*DD + n0 + mm];
        }
        __syncthreads();
        #pragma unroll
        for (int kk = 0; kk < 16; kk++) {
            float4 aC = *reinterpret_cast<const float4*>(&sc[kk][ty*4]);
            float4 aS = *reinterpret_cast<const float4*>(&ss[kk][ty*4]);
            float4 bQ = *reinterpret_cast<const float4*>(&sq[kk][tx*4]);
            float ac[4] = {aC.x,aC.y,aC.z,aC.w};
            float as[4] = {aS.x,aS.y,aS.z,aS.w};
            float bq[4] = {bQ.x,bQ.y,bQ.z,bQ.w};
            #pragma unroll
            for (int i = 0; i < 4; i++)
                #pragma unroll
                for (int j = 0; j < 4; j++) {
                    accC[i][j] += ac[i] * bq[j];
                    accS[i][j] += as[i] * bq[j];
                }
        }
        __syncthreads();
    }
    #pragma unroll
    for (int i = 0; i < 4; i++) {
        int gm = m0 + ty*4 + i;
        if (gm < KP) {
            float Gv = g_G[b*KP + gm];
            int base = (b*KP + gm)*DD + n0 + tx*4;
            #pragma unroll
            for (int j = 0; j < 4; j++) {
                g_Sc[base+j] = Gv * accC[i][j];
                g_Ss[base+j] = Gv * accS[i][j];
            }
        }
    }
}

/* ---------------- NN fused: pot += c@(G Sc) + s@(G Ss) -------------------- */
__global__ void k_pot() {
    __shared__ float ac_[64][17];
    __shared__ float as_[64][17];
    __shared__ float bc[16][64];
    __shared__ float bs[16][64];
    int b  = blockIdx.z;
    int m0 = blockIdx.x * 64;   /* atom tile    */
    int n0 = blockIdx.y * 64;   /* channel tile */
    int tid = threadIdx.x, tx = tid & 15, ty = tid >> 4;
    const float* cosb = g_cos + (size_t)b * NA * KP;
    const float* sinb = g_sin + (size_t)b * NA * KP;
    float acc[4][4] = {};
    for (int kt = 0; kt < KP; kt += 16) {   /* 138 exact iterations */
        #pragma unroll
        for (int l = tid; l < 1024; l += 256) {
            int kkA = l & 15, mmA = l >> 4;
            int gm = m0 + mmA;
            float vc = 0.f, vs = 0.f;
            if (gm < NA) {
                size_t off = (size_t)gm * KP + kt + kkA;
                vc = cosb[off]; vs = sinb[off];
            }
            ac_[mmA][kkA] = vc;
            as_[mmA][kkA] = vs;
            int nnB = l & 63, kkB = l >> 6;
            int sidx = (b*KP + kt + kkB)*DD + n0 + nnB;
            bc[kkB][nnB] = g_Sc[sidx];
            bs[kkB][nnB] = g_Ss[sidx];
        }
        __syncthreads();
        #pragma unroll
        for (int kk = 0; kk < 16; kk++) {
            float a_c[4], a_s[4];
            #pragma unroll
            for (int i = 0; i < 4; i++) { a_c[i] = ac_[ty*4+i][kk]; a_s[i] = as_[ty*4+i][kk]; }
            float4 bC = *reinterpret_cast<const float4*>(&bc[kk][tx*4]);
            float4 bS = *reinterpret_cast<const float4*>(&bs[kk][tx*4]);
            float bcv[4] = {bC.x,bC.y,bC.z,bC.w};
            float bsv[4] = {bS.x,bS.y,bS.z,bS.w};
            #pragma unroll
            for (int i = 0; i < 4; i++)
                #pragma unroll
                for (int j = 0; j < 4; j++)
                    acc[i][j] += a_c[i]*bcv[j] + a_s[i]*bsv[j];
        }
        __syncthreads();
    }
    #pragma unroll
    for (int i = 0; i < 4; i++) {
        int gm = m0 + ty*4 + i;
        if (gm < NA) {
            int base = (b*NA + gm)*DD + n0 + tx*4;
            #pragma unroll
            for (int j = 0; j < 4; j++) g_pot[base+j] += acc[i][j];
        }
    }
}

/* ---------------- out = (pot + self*q) * q -------------------------------- */
__global__ void k_final(float* __restrict__ out) {
    int idx = blockIdx.x * blockDim.x + threadIdx.x;
    float qv = g_q[idx];
    out[idx] = (g_pot[idx] + C_SELF * qv) * qv;
}

/* ---------------- launch -------------------------------------------------- */
extern "C" void kernel_launch(void* const* d_in, const int* in_sizes, int n_in,
                              void* d_out, int out_size) {
    const float* features = (const float*)d_in[0];
    const float* positions= (const float*)d_in[1];
    const float* cell     = (const float*)d_in[2];
    const int*   nbidx    = (const int*)  d_in[3];
    const float* nbdist   = (const float*)d_in[4];
    const float* W        = (const float*)d_in[5];
    const float* bias     = (const float*)d_in[6];
    float* out = (float*)d_out;

    k_kG     <<<dim3((KP+255)/256, BB), 256>>>(cell);
    k_charges<<<dim3((BB*NA)/64, DD/64), 256>>>(features, W, bias);
    k_zero   <<<(BB*NA*DD)/256, 256>>>();
    k_phase  <<<BB*NA, 256>>>(positions);
    k_edges  <<<(BB*EE)/8, 256>>>(nbidx, nbdist);
    k_sf     <<<dim3((KP+63)/64, DD/64, BB), 256>>>();
    k_pot    <<<dim3((NA+63)/64, DD/64, BB), 256>>>();
    k_final  <<<(BB*NA*DD)/256, 256>>>(out);
    (void)in_sizes; (void)n_in; (void)out_size;
}

// round 2
// speedup vs baseline: 2.5670x; 2.5670x over previous
#include <cuda_runtime.h>
#include <math.h>

#define BB 8
#define NA 2000
#define DD 256
#define EE 64000
#define KNUM 2196
#define KP 2240          /* 64 * 35, padded with G=0, cos/sin=0 */
#define PI_F 3.14159265358979f
#define C_SELF (-0.7978845608028654f)   /* -sqrt(2/pi)/sigma */

/* ---------------- scratch (device globals; no allocations allowed) -------- */
__device__ float g_q  [BB*NA*DD];
__device__ float g_pot[BB*NA*DD];
__device__ float g_cos[(size_t)BB*NA*KP];
__device__ float g_sin[(size_t)BB*NA*KP];
__device__ float g_Sc [BB*KP*DD];
__device__ float g_Ss [BB*KP*DD];
__device__ float g_G  [BB*KP];
__device__ float g_kv [BB*KP*3];
__device__ int   g_cnt[BB*NA];
__device__ int   g_off[BB*NA];
__device__ int   g_fil[BB*NA];
__device__ int   g_elj[BB*EE];
__device__ float g_elv[BB*EE];

__device__ __forceinline__ unsigned f2tf(float x) {
    unsigned r; asm("cvt.rna.tf32.f32 %0, %1;" : "=r"(r) : "f"(x)); return r;
}
__device__ __forceinline__ void mma_tf32(float* d, unsigned a0, unsigned a1,
                                         unsigned a2, unsigned a3,
                                         unsigned b0, unsigned b1) {
    asm volatile(
        "mma.sync.aligned.m16n8k8.row.col.f32.tf32.tf32.f32 "
        "{%0,%1,%2,%3},{%4,%5,%6,%7},{%8,%9},{%0,%1,%2,%3};"
        : "+f"(d[0]), "+f"(d[1]), "+f"(d[2]), "+f"(d[3])
        : "r"(a0), "r"(a1), "r"(a2), "r"(a3), "r"(b0), "r"(b1));
}

/* ---------------- k-vectors + Green's function ---------------------------- */
__global__ void k_kG(const float* __restrict__ cell) {
    int k = blockIdx.x * blockDim.x + threadIdx.x;
    int b = blockIdx.y;
    if (k >= KP) return;
    const float* C = cell + b * 9;
    float c00=C[0],c01=C[1],c02=C[2];
    float c10=C[3],c11=C[4],c12=C[5];
    float c20=C[6],c21=C[7],c22=C[8];
    float det = c00*(c11*c22-c12*c21) - c01*(c10*c22-c12*c20) + c02*(c10*c21-c11*c20);
    float id = 1.0f/det;
    float i00=(c11*c22-c12*c21)*id, i01=(c02*c21-c01*c22)*id, i02=(c01*c12-c02*c11)*id;
    float i10=(c12*c20-c10*c22)*id, i11=(c00*c22-c02*c20)*id, i12=(c02*c10-c00*c12)*id;
    float i20=(c10*c21-c11*c20)*id, i21=(c01*c20-c00*c21)*id, i22=(c00*c11-c01*c10)*id;
    float kx=0.f, ky=0.f, kz=0.f, G=0.f;
    if (k < KNUM) {
        int m = k + (k >= 1098);               /* skip the (0,0,0) row */
        float ni = (float)(m/169 - 6);
        float nj = (float)((m/13)%13 - 6);
        float nk = (float)(m%13 - 6);
        kx = 2.0f*PI_F*(i00*ni + i01*nj + i02*nk);
        ky = 2.0f*PI_F*(i10*ni + i11*nj + i12*nk);
        kz = 2.0f*PI_F*(i20*ni + i21*nj + i22*nk);
        float k2 = kx*kx + ky*ky + kz*kz;
        G = 4.0f*PI_F/fabsf(det) * __expf(-0.5f*k2) / k2;   /* sigma = 1 */
    }
    g_kv[(b*KP + k)*3 + 0] = kx;
    g_kv[(b*KP + k)*3 + 1] = ky;
    g_kv[(b*KP + k)*3 + 2] = kz;
    g_G [ b*KP + k]        = G;
}

/* ---------------- charges = features @ W^T + b (fp32 NT SGEMM) ------------ */
__global__ void k_charges(const float* __restrict__ A, const float* __restrict__ Wm,
                          const float* __restrict__ bias) {
    __shared__ float As[64][17];
    __shared__ float Bs[64][17];
    int m0 = blockIdx.x * 64, n0 = blockIdx.y * 64;
    int tid = threadIdx.x, tx = tid & 15, ty = tid >> 4;
    float acc[4][4] = {};
    for (int kt = 0; kt < 256; kt += 16) {
        #pragma unroll
        for (int l = tid; l < 1024; l += 256) {
            int kk = l & 15, mm = l >> 4;
            As[mm][kk] = A [(m0+mm)*256 + kt + kk];
            Bs[mm][kk] = Wm[(n0+mm)*256 + kt + kk];
        }
        __syncthreads();
        #pragma unroll
        for (int kk = 0; kk < 16; kk++) {
            float a[4], bv[4];
            #pragma unroll
            for (int i = 0; i < 4; i++) { a[i]  = As[ty*4+i][kk]; bv[i] = Bs[tx*4+i][kk]; }
            #pragma unroll
            for (int i = 0; i < 4; i++)
                #pragma unroll
                for (int j = 0; j < 4; j++) acc[i][j] += a[i] * bv[j];
        }
        __syncthreads();
    }
    #pragma unroll
    for (int i = 0; i < 4; i++)
        #pragma unroll
        for (int j = 0; j < 4; j++)
            g_q[(m0+ty*4+i)*256 + n0+tx*4+j] = acc[i][j] + bias[n0+tx*4+j];
}

/* ---------------- phases: cos/sin(pos . kvec) ----------------------------- */
__global__ void k_phase(const float* __restrict__ pos) {
    int bn = blockIdx.x;
    int b  = bn / NA;
    float x = pos[bn*3+0], y = pos[bn*3+1], z = pos[bn*3+2];
    const float* kv = g_kv + b * KP * 3;
    size_t base = (size_t)bn * KP;
    for (int k = threadIdx.x; k < KP; k += 256) {
        float c = 0.f, s = 0.f;
        if (k < KNUM) {
            float ph = x*kv[k*3] + y*kv[k*3+1] + z*kv[k*3+2];
            __sincosf(ph, &s, &c);
        }
        g_cos[base + k] = c;
        g_sin[base + k] = s;
    }
}

/* ---------------- edge pipeline: count -> scan -> fill -> gather ----------- */
__global__ void k_init0() {
    int idx = blockIdx.x * blockDim.x + threadIdx.x;
    if (idx < BB*NA) g_cnt[idx] = 0;
    else             g_fil[idx - BB*NA] = 0;
}

__global__ void k_count(const int* __restrict__ nbidx) {
    int e = blockIdx.x * blockDim.x + threadIdx.x;
    if (e >= BB*EE) return;
    int b = e / EE;
    int i = nbidx[e*2];
    atomicAdd(&g_cnt[b*NA + i], 1);
}

/* Blelloch exclusive scan over 2048 slots, one block per batch */
__global__ void k_scan() {
    __shared__ int s[2048];
    int b = blockIdx.x, tid = threadIdx.x;
    #pragma unroll
    for (int i = 0; i < 2; i++) {
        int idx = tid + i*1024;
        s[idx] = (idx < NA) ? g_cnt[b*NA + idx] : 0;
    }
    int offset = 1;
    for (int d = 1024; d > 0; d >>= 1) {
        __syncthreads();
        if (tid < d) {
            int ai = offset*(2*tid+1) - 1;
            int bi = offset*(2*tid+2) - 1;
            s[bi] += s[ai];
        }
        offset <<= 1;
    }
    if (tid == 0) s[2047] = 0;
    for (int d = 1; d < 2048; d <<= 1) {
        offset >>= 1;
        __syncthreads();
        if (tid < d) {
            int ai = offset*(2*tid+1) - 1;
            int bi = offset*(2*tid+2) - 1;
            int t = s[ai]; s[ai] = s[bi]; s[bi] += t;
        }
    }
    __syncthreads();
    #pragma unroll
    for (int i = 0; i < 2; i++) {
        int idx = tid + i*1024;
        if (idx < NA) g_off[b*NA + idx] = s[idx];
    }
}

__global__ void k_fill(const int* __restrict__ nbidx, const float* __restrict__ nbdist) {
    int e = blockIdx.x * blockDim.x + threadIdx.x;
    if (e >= BB*EE) return;
    int b = e / EE;
    int i = nbidx[e*2 + 0];
    int j = nbidx[e*2 + 1];
    float d = nbdist[e];
    float v  = erfcf(d * 0.70710678118f) / d;
    float fc = (d < 5.0f) ? 0.5f*(__cosf(PI_F * d * 0.2f) + 1.0f) : 0.0f;
    float vsr = v - fc / d;
    int pos = g_off[b*NA + i] + atomicAdd(&g_fil[b*NA + i], 1);
    g_elj[b*EE + pos] = j;
    g_elv[b*EE + pos] = vsr;
}

/* one block per atom; thread = channel; writes pot (overwrites poison) */
__global__ void k_gather() {
    int bn = blockIdx.x;
    int b  = bn / NA;
    int tid = threadIdx.x;
    int start = g_off[bn];
    int cnt   = g_cnt[bn];
    const int*   ej = g_elj + b*EE + start;
    const float* ev = g_elv + b*EE + start;
    const float* qb = g_q + (size_t)b*NA*DD;
    float acc = 0.f;
    int e = 0;
    for (; e + 2 <= cnt; e += 2) {
        int   j0 = ej[e],   j1 = ej[e+1];
        float v0 = ev[e],   v1 = ev[e+1];
        acc += v0 * qb[(size_t)j0*DD + tid];
        acc += v1 * qb[(size_t)j1*DD + tid];
    }
    if (e < cnt) acc += ev[e] * qb[(size_t)ej[e]*DD + tid];
    g_pot[(size_t)bn*DD + tid] = acc;
}

/* ---------------- TF32 TN fused: Sc = G*(c^T q), Ss = G*(s^T q) ------------ */
/* grid (35, 4, 8), 128 threads. M=kvec(2240), N=chan(256), K=atoms(2000). */
__global__ void k_sf() {
    __shared__ unsigned sAc[16][72];   /* [atom][kvec-m]  */
    __shared__ unsigned sAs[16][72];
    __shared__ unsigned sB [16][72];   /* [atom][chan-n]  */
    int b  = blockIdx.z;
    int m0 = blockIdx.x * 64;
    int n0 = blockIdx.y * 64;
    int tid = threadIdx.x, warp = tid >> 5, lane = tid & 31;
    int tg = lane & 3, gp = lane >> 2;
    const float* cosb = g_cos + (size_t)b * NA * KP;
    const float* sinb = g_sin + (size_t)b * NA * KP;
    const float* qb   = g_q   + (size_t)b * NA * DD;
    float accC[8][4] = {}, accS[8][4] = {};
    for (int nt = 0; nt < NA; nt += 16) {
        #pragma unroll
        for (int i = 0; i < 2; i++) {
            int t = tid + i*128;
            int row = t >> 4, c4 = (t & 15) * 4;
            float4 vc = *(const float4*)&cosb[(size_t)(nt+row)*KP + m0 + c4];
            float4 vs = *(const float4*)&sinb[(size_t)(nt+row)*KP + m0 + c4];
            float4 vq = *(const float4*)&qb[(size_t)(nt+row)*DD + n0 + c4];
            sAc[row][c4+0]=f2tf(vc.x); sAc[row][c4+1]=f2tf(vc.y);
            sAc[row][c4+2]=f2tf(vc.z); sAc[row][c4+3]=f2tf(vc.w);
            sAs[row][c4+0]=f2tf(vs.x); sAs[row][c4+1]=f2tf(vs.y);
            sAs[row][c4+2]=f2tf(vs.z); sAs[row][c4+3]=f2tf(vs.w);
            sB [row][c4+0]=f2tf(vq.x); sB [row][c4+1]=f2tf(vq.y);
            sB [row][c4+2]=f2tf(vq.z); sB [row][c4+3]=f2tf(vq.w);
        }
        __syncthreads();
        #pragma unroll
        for (int k0 = 0; k0 < 16; k0 += 8) {
            int mb = warp*16;
            unsigned ac0 = sAc[k0+tg  ][mb+gp],   ac1 = sAc[k0+tg  ][mb+8+gp];
            unsigned ac2 = sAc[k0+tg+4][mb+gp],   ac3 = sAc[k0+tg+4][mb+8+gp];
            unsigned as0 = sAs[k0+tg  ][mb+gp],   as1 = sAs[k0+tg  ][mb+8+gp];
            unsigned as2 = sAs[k0+tg+4][mb+gp],   as3 = sAs[k0+tg+4][mb+8+gp];
            #pragma unroll
            for (int n8 = 0; n8 < 8; n8++) {
                unsigned b0 = sB[k0+tg  ][n8*8+gp];
                unsigned b1 = sB[k0+tg+4][n8*8+gp];
                mma_tf32(accC[n8], ac0, ac1, ac2, ac3, b0, b1);
                mma_tf32(accS[n8], as0, as1, as2, as3, b0, b1);
            }
        }
        __syncthreads();
    }
    int gm0 = m0 + warp*16 + gp;
    int gm1 = gm0 + 8;
    float G0 = g_G[b*KP + gm0];
    float G1 = g_G[b*KP + gm1];
    #pragma unroll
    for (int n8 = 0; n8 < 8; n8++) {
        int gn = n0 + n8*8 + tg*2;
        float2* pc0 = (float2*)&g_Sc[(size_t)(b*KP+gm0)*DD + gn];
        float2* pc1 = (float2*)&g_Sc[(size_t)(b*KP+gm1)*DD + gn];
        float2* ps0 = (float2*)&g_Ss[(size_t)(b*KP+gm0)*DD + gn];
        float2* ps1 = (float2*)&g_Ss[(size_t)(b*KP+gm1)*DD + gn];
        *pc0 = make_float2(G0*accC[n8][0], G0*accC[n8][1]);
        *pc1 = make_float2(G1*accC[n8][2], G1*accC[n8][3]);
        *ps0 = make_float2(G0*accS[n8][0], G0*accS[n8][1]);
        *ps1 = make_float2(G1*accS[n8][2], G1*accS[n8][3]);
    }
}

/* ---------------- TF32 NN fused: pot += c@Sc + s@Ss ------------------------ */
/* grid (32, 4, 8), 128 threads. M=atoms(2000), N=chan(256), K=kvec(2240). */
__global__ void k_pot() {
    __shared__ unsigned sAc[64][20];   /* [atom-m][kvec]  */
    __shared__ unsigned sAs[64][20];
    __shared__ unsigned sBc[16][72];   /* [kvec][chan-n]  */
    __shared__ unsigned sBs[16][72];
    int b  = blockIdx.z;
    int m0 = blockIdx.x * 64;
    int n0 = blockIdx.y * 64;
    int tid = threadIdx.x, warp = tid >> 5, lane = tid & 31;
    int tg = lane & 3, gp = lane >> 2;
    const float* cosb = g_cos + (size_t)b * NA * KP;
    const float* sinb = g_sin + (size_t)b * NA * KP;
    float acc[8][4] = {};
    for (int kt = 0; kt < KP; kt += 16) {
        #pragma unroll
        for (int i = 0; i < 2; i++) {
            int t = tid + i*128;
            int row = t >> 2, c4 = (t & 3) * 4;
            int gm = m0 + row;
            float4 vc = make_float4(0.f,0.f,0.f,0.f), vs = vc;
            if (gm < NA) {
                vc = *(const float4*)&cosb[(size_t)gm*KP + kt + c4];
                vs = *(const float4*)&sinb[(size_t)gm*KP + kt + c4];
            }
            sAc[row][c4+0]=f2tf(vc.x); sAc[row][c4+1]=f2tf(vc.y);
            sAc[row][c4+2]=f2tf(vc.z); sAc[row][c4+3]=f2tf(vc.w);
            sAs[row][c4+0]=f2tf(vs.x); sAs[row][c4+1]=f2tf(vs.y);
            sAs[row][c4+2]=f2tf(vs.z); sAs[row][c4+3]=f2tf(vs.w);
        }
        #pragma unroll
        for (int i = 0; i < 2; i++) {
            int t = tid + i*128;
            int row = t >> 4, c4 = (t & 15) * 4;
            size_t src = (size_t)(b*KP + kt + row)*DD + n0 + c4;
            float4 vc = *(const float4*)&g_Sc[src];
            float4 vs = *(const float4*)&g_Ss[src];
            sBc[row][c4+0]=f2tf(vc.x); sBc[row][c4+1]=f2tf(vc.y);
            sBc[row][c4+2]=f2tf(vc.z); sBc[row][c4+3]=f2tf(vc.w);
            sBs[row][c4+0]=f2tf(vs.x); sBs[row][c4+1]=f2tf(vs.y);
            sBs[row][c4+2]=f2tf(vs.z); sBs[row][c4+3]=f2tf(vs.w);
        }
        __syncthreads();
        #pragma unroll
        for (int k0 = 0; k0 < 16; k0 += 8) {
            int mb = warp*16;
            unsigned ac0 = sAc[mb+gp  ][k0+tg],   ac1 = sAc[mb+8+gp][k0+tg];
            unsigned ac2 = sAc[mb+gp  ][k0+tg+4], ac3 = sAc[mb+8+gp][k0+tg+4];
            unsigned as0 = sAs[mb+gp  ][k0+tg],   as1 = sAs[mb+8+gp][k0+tg];
            unsigned as2 = sAs[mb+gp  ][k0+tg+4], as3 = sAs[mb+8+gp][k0+tg+4];
            #pragma unroll
            for (int n8 = 0; n8 < 8; n8++) {
                unsigned bc0 = sBc[k0+tg  ][n8*8+gp];
                unsigned bc1 = sBc[k0+tg+4][n8*8+gp];
                unsigned bs0 = sBs[k0+tg  ][n8*8+gp];
                unsigned bs1 = sBs[k0+tg+4][n8*8+gp];
                mma_tf32(acc[n8], ac0, ac1, ac2, ac3, bc0, bc1);
                mma_tf32(acc[n8], as0, as1, as2, as3, bs0, bs1);
            }
        }
        __syncthreads();
    }
    int gm0 = m0 + warp*16 + gp;
    int gm1 = gm0 + 8;
    #pragma unroll
    for (int n8 = 0; n8 < 8; n8++) {
        int gn = n0 + n8*8 + tg*2;
        if (gm0 < NA) {
            float2* p = (float2*)&g_pot[(size_t)(b*NA+gm0)*DD + gn];
            float2 v = *p; v.x += acc[n8][0]; v.y += acc[n8][1]; *p = v;
        }
        if (gm1 < NA) {
            float2* p = (float2*)&g_pot[(size_t)(b*NA+gm1)*DD + gn];
            float2 v = *p; v.x += acc[n8][2]; v.y += acc[n8][3]; *p = v;
        }
    }
}

/* ---------------- out = (pot + self*q) * q -------------------------------- */
__global__ void k_final(float* __restrict__ out) {
    int idx = blockIdx.x * blockDim.x + threadIdx.x;
    float qv = g_q[idx];
    out[idx] = (g_pot[idx] + C_SELF * qv) * qv;
}

/* ---------------- launch -------------------------------------------------- */
extern "C" void kernel_launch(void* const* d_in, const int* in_sizes, int n_in,
                              void* d_out, int out_size) {
    const float* features = (const float*)d_in[0];
    const float* positions= (const float*)d_in[1];
    const float* cell     = (const float*)d_in[2];
    const int*   nbidx    = (const int*)  d_in[3];
    const float* nbdist   = (const float*)d_in[4];
    const float* W        = (const float*)d_in[5];
    const float* bias     = (const float*)d_in[6];
    float* out = (float*)d_out;

    k_kG     <<<dim3((KP+255)/256, BB), 256>>>(cell);
    k_charges<<<dim3((BB*NA)/64, DD/64), 256>>>(features, W, bias);
    k_phase  <<<BB*NA, 256>>>(positions);
    k_init0  <<<(2*BB*NA+255)/256, 256>>>();
    k_count  <<<(BB*EE+255)/256, 256>>>(nbidx);
    k_scan   <<<BB, 1024>>>();
    k_fill   <<<(BB*EE+255)/256, 256>>>(nbidx, nbdist);
    k_gather <<<BB*NA, 256>>>();
    k_sf     <<<dim3(KP/64, DD/64, BB), 128>>>();
    k_pot    <<<dim3((NA+63)/64, DD/64, BB), 128>>>();
    k_final  <<<(BB*NA*DD)/256, 256>>>(out);
    (void)in_sizes; (void)n_in; (void)out_size;
}

// round 3
// speedup vs baseline: 4.0626x; 1.5826x over previous
#include <cuda_runtime.h>
#include <cuda_fp16.h>
#include <math.h>

#define BB 8
#define NA 2000
#define DD 256
#define EE 64000
#define KNUM 2196
#define KP 2240          /* 64 * 35, padded with G=0, cos/sin=0 */
#define PI_F 3.14159265358979f
#define C_SELF (-0.7978845608028654f)   /* -sqrt(2/pi)/sigma */

/* ---------------- scratch (device globals; no allocations allowed) -------- */
__device__ float g_q  [BB*NA*DD];
__device__ float g_pot[BB*NA*DD];
__device__ __align__(16) half g_qh  [BB*NA*DD];
__device__ __align__(16) half g_cosh[(size_t)BB*NA*KP];
__device__ __align__(16) half g_sinh[(size_t)BB*NA*KP];
__device__ __align__(16) half g_Sch [BB*KP*DD];
__device__ __align__(16) half g_Ssh [BB*KP*DD];
__device__ float g_G  [BB*KP];
__device__ float g_kv [BB*KP*3];
__device__ int   g_cnt[BB*NA];
__device__ int   g_off[BB*NA];
__device__ int   g_fil[BB*NA];
__device__ int   g_elj[BB*EE];
__device__ float g_elv[BB*EE];

/* ---------------- MMA / ldmatrix helpers ----------------------------------- */
__device__ __forceinline__ unsigned sptr(const void* p) {
    return (unsigned)__cvta_generic_to_shared(p);
}
__device__ __forceinline__ void ldsm4(unsigned* r, unsigned a) {
    asm volatile("ldmatrix.sync.aligned.m8n8.x4.shared.b16 {%0,%1,%2,%3},[%4];"
        : "=r"(r[0]), "=r"(r[1]), "=r"(r[2]), "=r"(r[3]) : "r"(a));
}
__device__ __forceinline__ void ldsm4t(unsigned* r, unsigned a) {
    asm volatile("ldmatrix.sync.aligned.m8n8.x4.trans.shared.b16 {%0,%1,%2,%3},[%4];"
        : "=r"(r[0]), "=r"(r[1]), "=r"(r[2]), "=r"(r[3]) : "r"(a));
}
__device__ __forceinline__ void mma16816(float* d, const unsigned* a,
                                         unsigned b0, unsigned b1) {
    asm volatile(
        "mma.sync.aligned.m16n8k16.row.col.f32.f16.f16.f32 "
        "{%0,%1,%2,%3},{%4,%5,%6,%7},{%8,%9},{%0,%1,%2,%3};"
        : "+f"(d[0]), "+f"(d[1]), "+f"(d[2]), "+f"(d[3])
        : "r"(a[0]), "r"(a[1]), "r"(a[2]), "r"(a[3]), "r"(b0), "r"(b1));
}

/* ---------------- k-vectors + Green's function ---------------------------- */
__global__ void k_kG(const float* __restrict__ cell) {
    int k = blockIdx.x * blockDim.x + threadIdx.x;
    int b = blockIdx.y;
    if (k >= KP) return;
    const float* C = cell + b * 9;
    float c00=C[0],c01=C[1],c02=C[2];
    float c10=C[3],c11=C[4],c12=C[5];
    float c20=C[6],c21=C[7],c22=C[8];
    float det = c00*(c11*c22-c12*c21) - c01*(c10*c22-c12*c20) + c02*(c10*c21-c11*c20);
    float id = 1.0f/det;
    float i00=(c11*c22-c12*c21)*id, i01=(c02*c21-c01*c22)*id, i02=(c01*c12-c02*c11)*id;
    float i10=(c12*c20-c10*c22)*id, i11=(c00*c22-c02*c20)*id, i12=(c02*c10-c00*c12)*id;
    float i20=(c10*c21-c11*c20)*id, i21=(c01*c20-c00*c21)*id, i22=(c00*c11-c01*c10)*id;
    float kx=0.f, ky=0.f, kz=0.f, G=0.f;
    if (k < KNUM) {
        int m = k + (k >= 1098);               /* skip the (0,0,0) row */
        float ni = (float)(m/169 - 6);
        float nj = (float)((m/13)%13 - 6);
        float nk = (float)(m%13 - 6);
        kx = 2.0f*PI_F*(i00*ni + i01*nj + i02*nk);
        ky = 2.0f*PI_F*(i10*ni + i11*nj + i12*nk);
        kz = 2.0f*PI_F*(i20*ni + i21*nj + i22*nk);
        float k2 = kx*kx + ky*ky + kz*kz;
        G = 4.0f*PI_F/fabsf(det) * __expf(-0.5f*k2) / k2;   /* sigma = 1 */
    }
    g_kv[(b*KP + k)*3 + 0] = kx;
    g_kv[(b*KP + k)*3 + 1] = ky;
    g_kv[(b*KP + k)*3 + 2] = kz;
    g_G [ b*KP + k]        = G;
}

/* ---------------- charges = features @ W^T + b (fp32 NT SGEMM) ------------ */
__global__ void k_charges(const float* __restrict__ A, const float* __restrict__ Wm,
                          const float* __restrict__ bias) {
    __shared__ float As[64][17];
    __shared__ float Bs[64][17];
    int m0 = blockIdx.x * 64, n0 = blockIdx.y * 64;
    int tid = threadIdx.x, tx = tid & 15, ty = tid >> 4;
    float acc[4][4] = {};
    for (int kt = 0; kt < 256; kt += 16) {
        #pragma unroll
        for (int l = tid; l < 1024; l += 256) {
            int kk = l & 15, mm = l >> 4;
            As[mm][kk] = A [(m0+mm)*256 + kt + kk];
            Bs[mm][kk] = Wm[(n0+mm)*256 + kt + kk];
        }
        __syncthreads();
        #pragma unroll
        for (int kk = 0; kk < 16; kk++) {
            float a[4], bv[4];
            #pragma unroll
            for (int i = 0; i < 4; i++) { a[i]  = As[ty*4+i][kk]; bv[i] = Bs[tx*4+i][kk]; }
            #pragma unroll
            for (int i = 0; i < 4; i++)
                #pragma unroll
                for (int j = 0; j < 4; j++) acc[i][j] += a[i] * bv[j];
        }
        __syncthreads();
    }
    #pragma unroll
    for (int i = 0; i < 4; i++)
        #pragma unroll
        for (int j = 0; j < 4; j++) {
            float v = acc[i][j] + bias[n0+tx*4+j];
            int idx = (m0+ty*4+i)*256 + n0+tx*4+j;
            g_q [idx] = v;
            g_qh[idx] = __float2half(v);
        }
}

/* ---------------- phases: cos/sin(pos . kvec) -> fp16 ---------------------- */
__global__ void k_phase(const float* __restrict__ pos) {
    int bn = blockIdx.x;
    int b  = bn / NA;
    float x = pos[bn*3+0], y = pos[bn*3+1], z = pos[bn*3+2];
    const float* kv = g_kv + b * KP * 3;
    size_t base = (size_t)bn * KP;
    for (int k2 = threadIdx.x; k2 < KP/2; k2 += 256) {
        int k = k2 * 2;
        float c0=0.f, s0=0.f, c1=0.f, s1=0.f;
        if (k < KNUM) {
            float ph = x*kv[k*3] + y*kv[k*3+1] + z*kv[k*3+2];
            __sincosf(ph, &s0, &c0);
        }
        if (k+1 < KNUM) {
            float ph = x*kv[(k+1)*3] + y*kv[(k+1)*3+1] + z*kv[(k+1)*3+2];
            __sincosf(ph, &s1, &c1);
        }
        *(half2*)&g_cosh[base + k] = __floats2half2_rn(c0, c1);
        *(half2*)&g_sinh[base + k] = __floats2half2_rn(s0, s1);
    }
}

/* ---------------- edge pipeline: count -> scan -> fill -> gather ----------- */
__global__ void k_init0() {
    int idx = blockIdx.x * blockDim.x + threadIdx.x;
    if (idx < BB*NA) g_cnt[idx] = 0;
    else             g_fil[idx - BB*NA] = 0;
}

__global__ void k_count(const int* __restrict__ nbidx) {
    int e = blockIdx.x * blockDim.x + threadIdx.x;
    if (e >= BB*EE) return;
    int b = e / EE;
    int i = nbidx[e*2];
    atomicAdd(&g_cnt[b*NA + i], 1);
}

__global__ void k_scan() {
    __shared__ int s[2048];
    int b = blockIdx.x, tid = threadIdx.x;
    #pragma unroll
    for (int i = 0; i < 2; i++) {
        int idx = tid + i*1024;
        s[idx] = (idx < NA) ? g_cnt[b*NA + idx] : 0;
    }
    int offset = 1;
    for (int d = 1024; d > 0; d >>= 1) {
        __syncthreads();
        if (tid < d) {
            int ai = offset*(2*tid+1) - 1;
            int bi = offset*(2*tid+2) - 1;
            s[bi] += s[ai];
        }
        offset <<= 1;
    }
    if (tid == 0) s[2047] = 0;
    for (int d = 1; d < 2048; d <<= 1) {
        offset >>= 1;
        __syncthreads();
        if (tid < d) {
            int ai = offset*(2*tid+1) - 1;
            int bi = offset*(2*tid+2) - 1;
            int t = s[ai]; s[ai] = s[bi]; s[bi] += t;
        }
    }
    __syncthreads();
    #pragma unroll
    for (int i = 0; i < 2; i++) {
        int idx = tid + i*1024;
        if (idx < NA) g_off[b*NA + idx] = s[idx];
    }
}

__global__ void k_fill(const int* __restrict__ nbidx, const float* __restrict__ nbdist) {
    int e = blockIdx.x * blockDim.x + threadIdx.x;
    if (e >= BB*EE) return;
    int b = e / EE;
    int i = nbidx[e*2 + 0];
    int j = nbidx[e*2 + 1];
    float d = nbdist[e];
    float v  = erfcf(d * 0.70710678118f) / d;
    float fc = (d < 5.0f) ? 0.5f*(__cosf(PI_F * d * 0.2f) + 1.0f) : 0.0f;
    float vsr = v - fc / d;
    int pos = g_off[b*NA + i] + atomicAdd(&g_fil[b*NA + i], 1);
    g_elj[b*EE + pos] = j;
    g_elv[b*EE + pos] = vsr;
}

__global__ void k_gather() {
    int bn = blockIdx.x;
    int b  = bn / NA;
    int tid = threadIdx.x;
    int start = g_off[bn];
    int cnt   = g_cnt[bn];
    const int*   ej = g_elj + b*EE + start;
    const float* ev = g_elv + b*EE + start;
    const float* qb = g_q + (size_t)b*NA*DD;
    float acc = 0.f;
    int e = 0;
    for (; e + 2 <= cnt; e += 2) {
        int   j0 = ej[e],   j1 = ej[e+1];
        float v0 = ev[e],   v1 = ev[e+1];
        acc += v0 * qb[(size_t)j0*DD + tid];
        acc += v1 * qb[(size_t)j1*DD + tid];
    }
    if (e < cnt) acc += ev[e] * qb[(size_t)ej[e]*DD + tid];
    g_pot[(size_t)bn*DD + tid] = acc;
}

/* ---------------- fp16 TN fused: Sc = G*(c^T q), Ss = G*(s^T q) ------------ */
/* grid (35, 4, 8), 128 threads. M=kvec(2240), N=chan(256), K=atoms(2000). */
__global__ void k_sf() {
    __shared__ __align__(16) half sc[16][72];   /* [atom-k][kvec-m] */
    __shared__ __align__(16) half ss[16][72];
    __shared__ __align__(16) half sq[16][72];   /* [atom-k][chan-n] */
    int b  = blockIdx.z;
    int m0 = blockIdx.x * 64;
    int n0 = blockIdx.y * 64;
    int tid = threadIdx.x, warp = tid >> 5, lane = tid & 31;
    int tg = lane & 3, gp = lane >> 2;
    const half* cosb = g_cosh + (size_t)b * NA * KP;
    const half* sinb = g_sinh + (size_t)b * NA * KP;
    const half* qb   = g_qh   + (size_t)b * NA * DD;
    float accC[8][4] = {}, accS[8][4] = {};
    int lrow = tid >> 3, lc8 = (tid & 7) * 8;
    int mb = warp * 16;
    /* A fragment addrs (trans from [k][m] layout) */
    int arow = (lane & 7) + ((lane >> 4) << 3);
    int acol = mb + ((lane >> 3) & 1) * 8;
    unsigned aAc = sptr(&sc[arow][acol]);
    unsigned aAs = sptr(&ss[arow][acol]);
    /* B fragment addrs (trans from [k][n] layout), n-pairs p=0..3 */
    int brow = lane & 15, bc8 = ((lane >> 4) << 3);
    unsigned aB0 = sptr(&sq[brow][ 0 + bc8]);
    unsigned aB1 = sptr(&sq[brow][16 + bc8]);
    unsigned aB2 = sptr(&sq[brow][32 + bc8]);
    unsigned aB3 = sptr(&sq[brow][48 + bc8]);
    for (int nt = 0; nt < NA; nt += 16) {
        *(uint4*)&sc[lrow][lc8] = *(const uint4*)&cosb[(size_t)(nt+lrow)*KP + m0 + lc8];
        *(uint4*)&ss[lrow][lc8] = *(const uint4*)&sinb[(size_t)(nt+lrow)*KP + m0 + lc8];
        *(uint4*)&sq[lrow][lc8] = *(const uint4*)&qb  [(size_t)(nt+lrow)*DD + n0 + lc8];
        __syncthreads();
        unsigned ac[4], as_[4], bq[4];
        ldsm4t(ac,  aAc);
        ldsm4t(as_, aAs);
        ldsm4t(bq, aB0);
        mma16816(accC[0], ac,  bq[0], bq[1]);  mma16816(accS[0], as_, bq[0], bq[1]);
        mma16816(accC[1], ac,  bq[2], bq[3]);  mma16816(accS[1], as_, bq[2], bq[3]);
        ldsm4t(bq, aB1);
        mma16816(accC[2], ac,  bq[0], bq[1]);  mma16816(accS[2], as_, bq[0], bq[1]);
        mma16816(accC[3], ac,  bq[2], bq[3]);  mma16816(accS[3], as_, bq[2], bq[3]);
        ldsm4t(bq, aB2);
        mma16816(accC[4], ac,  bq[0], bq[1]);  mma16816(accS[4], as_, bq[0], bq[1]);
        mma16816(accC[5], ac,  bq[2], bq[3]);  mma16816(accS[5], as_, bq[2], bq[3]);
        ldsm4t(bq, aB3);
        mma16816(accC[6], ac,  bq[0], bq[1]);  mma16816(accS[6], as_, bq[0], bq[1]);
        mma16816(accC[7], ac,  bq[2], bq[3]);  mma16816(accS[7], as_, bq[2], bq[3]);
        __syncthreads();
    }
    int gm0 = m0 + mb + gp;
    int gm1 = gm0 + 8;
    float G0 = g_G[b*KP + gm0];
    float G1 = g_G[b*KP + gm1];
    #pragma unroll
    for (int n8 = 0; n8 < 8; n8++) {
        int gn = n0 + n8*8 + tg*2;
        *(half2*)&g_Sch[(size_t)(b*KP+gm0)*DD + gn] = __floats2half2_rn(G0*accC[n8][0], G0*accC[n8][1]);
        *(half2*)&g_Sch[(size_t)(b*KP+gm1)*DD + gn] = __floats2half2_rn(G1*accC[n8][2], G1*accC[n8][3]);
        *(half2*)&g_Ssh[(size_t)(b*KP+gm0)*DD + gn] = __floats2half2_rn(G0*accS[n8][0], G0*accS[n8][1]);
        *(half2*)&g_Ssh[(size_t)(b*KP+gm1)*DD + gn] = __floats2half2_rn(G1*accS[n8][2], G1*accS[n8][3]);
    }
}

/* ---------------- fp16 NN fused: pot += c@Sc + s@Ss ------------------------ */
/* grid (32, 4, 8), 128 threads. M=atoms(2000), N=chan(256), K=kvec(2240). */
__global__ void k_pot() {
    __shared__ __align__(16) half sAc[64][24];  /* [atom-m][kvec-k] */
    __shared__ __align__(16) half sAs[64][24];
    __shared__ __align__(16) half sBc[16][72];  /* [kvec-k][chan-n] */
    __shared__ __align__(16) half sBs[16][72];
    int b  = blockIdx.z;
    int m0 = blockIdx.x * 64;
    int n0 = blockIdx.y * 64;
    int tid = threadIdx.x, warp = tid >> 5, lane = tid & 31;
    int tg = lane & 3, gp = lane >> 2;
    const half* cosb = g_cosh + (size_t)b * NA * KP;
    const half* sinb = g_sinh + (size_t)b * NA * KP;
    float acc[8][4] = {};
    int Arow = tid >> 1, Ac8 = (tid & 1) * 8;
    int gmA = m0 + Arow;
    int Brow = tid >> 3, Bc8 = (tid & 7) * 8;
    int mb = warp * 16;
    /* A fragment addrs (no trans, [m][k] layout) */
    int g = lane >> 3, r = lane & 7;
    unsigned aAc_ = sptr(&sAc[mb + r + (g&1)*8][(g>>1)*8]);
    unsigned aAs_ = sptr(&sAs[mb + r + (g&1)*8][(g>>1)*8]);
    /* B fragment addrs (trans, [k][n] layout) */
    int brow = lane & 15, bc8 = ((lane >> 4) << 3);
    unsigned aBc0 = sptr(&sBc[brow][ 0 + bc8]), aBs0 = sptr(&sBs[brow][ 0 + bc8]);
    unsigned aBc1 = sptr(&sBc[brow][16 + bc8]), aBs1 = sptr(&sBs[brow][16 + bc8]);
    unsigned aBc2 = sptr(&sBc[brow][32 + bc8]), aBs2 = sptr(&sBs[brow][32 + bc8]);
    unsigned aBc3 = sptr(&sBc[brow][48 + bc8]), aBs3 = sptr(&sBs[brow][48 + bc8]);
    const uint4 z4 = make_uint4(0,0,0,0);
    for (int kt = 0; kt < KP; kt += 16) {
        uint4 vc = z4, vs = z4;
        if (gmA < NA) {
            vc = *(const uint4*)&cosb[(size_t)gmA*KP + kt + Ac8];
            vs = *(const uint4*)&sinb[(size_t)gmA*KP + kt + Ac8];
        }
        *(uint4*)&sAc[Arow][Ac8] = vc;
        *(uint4*)&sAs[Arow][Ac8] = vs;
        *(uint4*)&sBc[Brow][Bc8] = *(const uint4*)&g_Sch[(size_t)(b*KP+kt+Brow)*DD + n0 + Bc8];
        *(uint4*)&sBs[Brow][Bc8] = *(const uint4*)&g_Ssh[(size_t)(b*KP+kt+Brow)*DD + n0 + Bc8];
        __syncthreads();
        unsigned ac[4], as_[4], bb[4];
        ldsm4(ac,  aAc_);
        ldsm4(as_, aAs_);
        ldsm4t(bb, aBc0);
        mma16816(acc[0], ac, bb[0], bb[1]);  mma16816(acc[1], ac, bb[2], bb[3]);
        ldsm4t(bb, aBs0);
        mma16816(acc[0], as_, bb[0], bb[1]); mma16816(acc[1], as_, bb[2], bb[3]);
        ldsm4t(bb, aBc1);
        mma16816(acc[2], ac, bb[0], bb[1]);  mma16816(acc[3], ac, bb[2], bb[3]);
        ldsm4t(bb, aBs1);
        mma16816(acc[2], as_, bb[0], bb[1]); mma16816(acc[3], as_, bb[2], bb[3]);
        ldsm4t(bb, aBc2);
        mma16816(acc[4], ac, bb[0], bb[1]);  mma16816(acc[5], ac, bb[2], bb[3]);
        ldsm4t(bb, aBs2);
        mma16816(acc[4], as_, bb[0], bb[1]); mma16816(acc[5], as_, bb[2], bb[3]);
        ldsm4t(bb, aBc3);
        mma16816(acc[6], ac, bb[0], bb[1]);  mma16816(acc[7], ac, bb[2], bb[3]);
        ldsm4t(bb, aBs3);
        mma16816(acc[6], as_, bb[0], bb[1]); mma16816(acc[7], as_, bb[2], bb[3]);
        __syncthreads();
    }
    int gm0 = m0 + mb + gp;
    int gm1 = gm0 + 8;
    #pragma unroll
    for (int n8 = 0; n8 < 8; n8++) {
        int gn = n0 + n8*8 + tg*2;
        if (gm0 < NA) {
            float2* p = (float2*)&g_pot[(size_t)(b*NA+gm0)*DD + gn];
            float2 v = *p; v.x += acc[n8][0]; v.y += acc[n8][1]; *p = v;
        }
        if (gm1 < NA) {
            float2* p = (float2*)&g_pot[(size_t)(b*NA+gm1)*DD + gn];
            float2 v = *p; v.x += acc[n8][2]; v.y += acc[n8][3]; *p = v;
        }
    }
}

/* ---------------- out = (pot + self*q) * q -------------------------------- */
__global__ void k_final(float* __restrict__ out) {
    int idx = blockIdx.x * blockDim.x + threadIdx.x;
    float qv = g_q[idx];
    out[idx] = (g_pot[idx] + C_SELF * qv) * qv;
}

/* ---------------- launch -------------------------------------------------- */
extern "C" void kernel_launch(void* const* d_in, const int* in_sizes, int n_in,
                              void* d_out, int out_size) {
    const float* features = (const float*)d_in[0];
    const float* positions= (const float*)d_in[1];
    const float* cell     = (const float*)d_in[2];
    const int*   nbidx    = (const int*)  d_in[3];
    const float* nbdist   = (const float*)d_in[4];
    const float* W        = (const float*)d_in[5];
    const float* bias     = (const float*)d_in[6];
    float* out = (float*)d_out;

    k_kG     <<<dim3((KP+255)/256, BB), 256>>>(cell);
    k_charges<<<dim3((BB*NA)/64, DD/64), 256>>>(features, W, bias);
    k_phase  <<<BB*NA, 256>>>(positions);
    k_init0  <<<(2*BB*NA+255)/256, 256>>>();
    k_count  <<<(BB*EE+255)/256, 256>>>(nbidx);
    k_scan   <<<BB, 1024>>>();
    k_fill   <<<(BB*EE+255)/256, 256>>>(nbidx, nbdist);
    k_gather <<<BB*NA, 256>>>();
    k_sf     <<<dim3(KP/64, DD/64, BB), 128>>>();
    k_pot    <<<dim3((NA+63)/64, DD/64, BB), 128>>>();
    k_final  <<<(BB*NA*DD)/256, 256>>>(out);
    (void)in_sizes; (void)n_in; (void)out_size;
}

// round 4
// speedup vs baseline: 4.7318x; 1.1647x over previous
#include <cuda_runtime.h>
#include <cuda_fp16.h>
#include <math.h>

#define BB 8
#define NA 2000
#define DD 256
#define EE 64000
#define KNUM 2196
#define KP 2304          /* 128 * 18, padded with G=0, cos/sin=0 */
#define PI_F 3.14159265358979f
#define C_SELF (-0.7978845608028654f)   /* -sqrt(2/pi)/sigma */

/* ---------------- scratch (device globals; no allocations allowed) -------- */
__device__ float g_q  [BB*NA*DD];
__device__ float g_pot[BB*NA*DD];
__device__ __align__(16) half g_qh  [BB*NA*DD];
__device__ __align__(16) half g_cosh[(size_t)BB*NA*KP];
__device__ __align__(16) half g_sinh[(size_t)BB*NA*KP];
__device__ __align__(16) half g_Sch [BB*KP*DD];
__device__ __align__(16) half g_Ssh [BB*KP*DD];
__device__ float g_G  [BB*KP];
__device__ int   g_cnt[BB*NA];
__device__ int   g_off[BB*NA];
__device__ int   g_fil[BB*NA];
__device__ int   g_elj[BB*EE];
__device__ float g_elv[BB*EE];

/* ---------------- MMA / ldmatrix helpers ----------------------------------- */
__device__ __forceinline__ unsigned sptr(const void* p) {
    return (unsigned)__cvta_generic_to_shared(p);
}
__device__ __forceinline__ void ldsm4(unsigned* r, unsigned a) {
    asm volatile("ldmatrix.sync.aligned.m8n8.x4.shared.b16 {%0,%1,%2,%3},[%4];"
        : "=r"(r[0]), "=r"(r[1]), "=r"(r[2]), "=r"(r[3]) : "r"(a));
}
__device__ __forceinline__ void ldsm4t(unsigned* r, unsigned a) {
    asm volatile("ldmatrix.sync.aligned.m8n8.x4.trans.shared.b16 {%0,%1,%2,%3},[%4];"
        : "=r"(r[0]), "=r"(r[1]), "=r"(r[2]), "=r"(r[3]) : "r"(a));
}
__device__ __forceinline__ void mma16816(float* d, const unsigned* a,
                                         unsigned b0, unsigned b1) {
    asm volatile(
        "mma.sync.aligned.m16n8k16.row.col.f32.f16.f16.f32 "
        "{%0,%1,%2,%3},{%4,%5,%6,%7},{%8,%9},{%0,%1,%2,%3};"
        : "+f"(d[0]), "+f"(d[1]), "+f"(d[2]), "+f"(d[3])
        : "r"(a[0]), "r"(a[1]), "r"(a[2]), "r"(a[3]), "r"(b0), "r"(b1));
}
__device__ __forceinline__ unsigned f2tf(float x) {
    unsigned r; asm("cvt.rna.tf32.f32 %0, %1;" : "=r"(r) : "f"(x)); return r;
}
__device__ __forceinline__ void mma_tf32(float* d, unsigned a0, unsigned a1,
                                         unsigned a2, unsigned a3,
                                         unsigned b0, unsigned b1) {
    asm volatile(
        "mma.sync.aligned.m16n8k8.row.col.f32.tf32.tf32.f32 "
        "{%0,%1,%2,%3},{%4,%5,%6,%7},{%8,%9},{%0,%1,%2,%3};"
        : "+f"(d[0]), "+f"(d[1]), "+f"(d[2]), "+f"(d[3])
        : "r"(a0), "r"(a1), "r"(a2), "r"(a3), "r"(b0), "r"(b1));
}

/* ---------------- Green's function ----------------------------------------- */
__global__ void k_kG(const float* __restrict__ cell) {
    int k = blockIdx.x * blockDim.x + threadIdx.x;
    int b = blockIdx.y;
    if (k >= KP) return;
    const float* C = cell + b * 9;
    float c00=C[0],c01=C[1],c02=C[2];
    float c10=C[3],c11=C[4],c12=C[5];
    float c20=C[6],c21=C[7],c22=C[8];
    float det = c00*(c11*c22-c12*c21) - c01*(c10*c22-c12*c20) + c02*(c10*c21-c11*c20);
    float id = 1.0f/det;
    float i00=(c11*c22-c12*c21)*id, i01=(c02*c21-c01*c22)*id, i02=(c01*c12-c02*c11)*id;
    float i10=(c12*c20-c10*c22)*id, i11=(c00*c22-c02*c20)*id, i12=(c02*c10-c00*c12)*id;
    float i20=(c10*c21-c11*c20)*id, i21=(c01*c20-c00*c21)*id, i22=(c00*c11-c01*c10)*id;
    float G = 0.f;
    if (k < KNUM) {
        int m = k + (k >= 1098);               /* skip the (0,0,0) row */
        float ni = (float)(m/169 - 6);
        float nj = (float)((m/13)%13 - 6);
        float nk = (float)(m%13 - 6);
        float kx = 2.0f*PI_F*(i00*ni + i01*nj + i02*nk);
        float ky = 2.0f*PI_F*(i10*ni + i11*nj + i12*nk);
        float kz = 2.0f*PI_F*(i20*ni + i21*nj + i22*nk);
        float k2 = kx*kx + ky*ky + kz*kz;
        G = 4.0f*PI_F/fabsf(det) * __expf(-0.5f*k2) / k2;   /* sigma = 1 */
    }
    g_G[b*KP + k] = G;
}

/* ---------------- charges = features @ W^T + b (tf32 MMA) ------------------ */
/* grid (250, 4), 128 threads. tiles 64m x 64n, kt 16. */
__global__ void k_charges(const float* __restrict__ A, const float* __restrict__ Wm,
                          const float* __restrict__ bias) {
    __shared__ unsigned sA[64][20];   /* [m][k] tf32 */
    __shared__ unsigned sB[16][72];   /* [k][n] tf32 */
    int m0 = blockIdx.x * 64, n0 = blockIdx.y * 64;
    int tid = threadIdx.x, warp = tid >> 5, lane = tid & 31;
    int tg = lane & 3, gp = lane >> 2;
    int mb = warp * 16;
    float acc[8][4] = {};
    for (int kt = 0; kt < 256; kt += 16) {
        #pragma unroll
        for (int i = 0; i < 2; i++) {
            int t = tid + i*128;
            int row = t >> 2, k4 = (t & 3) * 4;
            float4 v = *(const float4*)&A[(size_t)(m0+row)*256 + kt + k4];
            sA[row][k4+0]=f2tf(v.x); sA[row][k4+1]=f2tf(v.y);
            sA[row][k4+2]=f2tf(v.z); sA[row][k4+3]=f2tf(v.w);
            float4 w = *(const float4*)&Wm[(size_t)(n0+row)*256 + kt + k4];
            sB[k4+0][row]=f2tf(w.x); sB[k4+1][row]=f2tf(w.y);
            sB[k4+2][row]=f2tf(w.z); sB[k4+3][row]=f2tf(w.w);
        }
        __syncthreads();
        #pragma unroll
        for (int k0 = 0; k0 < 16; k0 += 8) {
            unsigned a0 = sA[mb+gp  ][k0+tg],   a1 = sA[mb+8+gp][k0+tg];
            unsigned a2 = sA[mb+gp  ][k0+tg+4], a3 = sA[mb+8+gp][k0+tg+4];
            #pragma unroll
            for (int n8 = 0; n8 < 8; n8++) {
                unsigned b0 = sB[k0+tg  ][n8*8+gp];
                unsigned b1 = sB[k0+tg+4][n8*8+gp];
                mma_tf32(acc[n8], a0, a1, a2, a3, b0, b1);
            }
        }
        __syncthreads();
    }
    int gm0 = m0 + mb + gp, gm1 = gm0 + 8;
    #pragma unroll
    for (int n8 = 0; n8 < 8; n8++) {
        int gn = n0 + n8*8 + tg*2;
        float b0 = bias[gn], b1 = bias[gn+1];
        float v0 = acc[n8][0] + b0, v1 = acc[n8][1] + b1;
        float v2 = acc[n8][2] + b0, v3 = acc[n8][3] + b1;
        *(float2*)&g_q[(size_t)gm0*DD + gn] = make_float2(v0, v1);
        *(float2*)&g_q[(size_t)gm1*DD + gn] = make_float2(v2, v3);
        *(half2*)&g_qh[(size_t)gm0*DD + gn] = __floats2half2_rn(v0, v1);
        *(half2*)&g_qh[(size_t)gm1*DD + gn] = __floats2half2_rn(v2, v3);
    }
}

/* ---------------- phases via separable axis factors ------------------------ */
__global__ void k_phase(const float* __restrict__ pos, const float* __restrict__ cell) {
    __shared__ float er[3][13], ei[3][13];
    int bn = blockIdx.x;
    int b  = bn / NA;
    int tid = threadIdx.x;
    float px = pos[bn*3+0], py = pos[bn*3+1], pz = pos[bn*3+2];
    if (tid < 39) {
        const float* C = cell + b * 9;
        float c00=C[0],c01=C[1],c02=C[2];
        float c10=C[3],c11=C[4],c12=C[5];
        float c20=C[6],c21=C[7],c22=C[8];
        float det = c00*(c11*c22-c12*c21) - c01*(c10*c22-c12*c20) + c02*(c10*c21-c11*c20);
        float id = 1.0f/det;
        float i00=(c11*c22-c12*c21)*id, i01=(c02*c21-c01*c22)*id, i02=(c01*c12-c02*c11)*id;
        float i10=(c12*c20-c10*c22)*id, i11=(c00*c22-c02*c20)*id, i12=(c02*c10-c00*c12)*id;
        float i20=(c10*c21-c11*c20)*id, i21=(c01*c20-c00*c21)*id, i22=(c00*c11-c01*c10)*id;
        int axis = tid / 13, idx = tid % 13;
        float u;                               /* 2π * (column axis of inv) . p */
        if      (axis == 0) u = i00*px + i10*py + i20*pz;
        else if (axis == 1) u = i01*px + i11*py + i21*pz;
        else                u = i02*px + i12*py + i22*pz;
        float ph = 2.0f*PI_F * u * (float)(idx - 6);
        float s, c; __sincosf(ph, &s, &c);
        er[axis][idx] = c; ei[axis][idx] = s;
    }
    __syncthreads();
    size_t base = (size_t)bn * KP;
    for (int k2 = tid; k2 < KP/2; k2 += 256) {
        int k = k2 * 2;
        float c0=0.f, s0=0.f, c1=0.f, s1=0.f;
        #pragma unroll
        for (int h = 0; h < 2; h++) {
            int kk = k + h;
            if (kk < KNUM) {
                int m = kk + (kk >= 1098);
                int i = m / 169; int r = m - i*169;
                int j = r / 13;  int l = r - j*13;
                float ar = er[0][i], ai = ei[0][i];
                float br = er[1][j], bi = ei[1][j];
                float tr = ar*br - ai*bi, ti = ar*bi + ai*br;
                float cr = er[2][l], ci = ei[2][l];
                float cc = tr*cr - ti*ci, ss = tr*ci + ti*cr;
                if (h == 0) { c0 = cc; s0 = ss; } else { c1 = cc; s1 = ss; }
            }
        }
        *(half2*)&g_cosh[base + k] = __floats2half2_rn(c0, c1);
        *(half2*)&g_sinh[base + k] = __floats2half2_rn(s0, s1);
    }
}

/* ---------------- edge pipeline: count -> scan -> fill -> gather ----------- */
__global__ void k_init0() {
    int idx = blockIdx.x * blockDim.x + threadIdx.x;
    if (idx < BB*NA) g_cnt[idx] = 0;
    else             g_fil[idx - BB*NA] = 0;
}

__global__ void k_count(const int* __restrict__ nbidx) {
    int e = blockIdx.x * blockDim.x + threadIdx.x;
    if (e >= BB*EE) return;
    int b = e / EE;
    int i = nbidx[e*2];
    atomicAdd(&g_cnt[b*NA + i], 1);
}

__global__ void k_scan() {
    __shared__ int s[2048];
    int b = blockIdx.x, tid = threadIdx.x;
    #pragma unroll
    for (int i = 0; i < 2; i++) {
        int idx = tid + i*1024;
        s[idx] = (idx < NA) ? g_cnt[b*NA + idx] : 0;
    }
    int offset = 1;
    for (int d = 1024; d > 0; d >>= 1) {
        __syncthreads();
        if (tid < d) {
            int ai = offset*(2*tid+1) - 1;
            int bi = offset*(2*tid+2) - 1;
            s[bi] += s[ai];
        }
        offset <<= 1;
    }
    if (tid == 0) s[2047] = 0;
    for (int d = 1; d < 2048; d <<= 1) {
        offset >>= 1;
        __syncthreads();
        if (tid < d) {
            int ai = offset*(2*tid+1) - 1;
            int bi = offset*(2*tid+2) - 1;
            int t = s[ai]; s[ai] = s[bi]; s[bi] += t;
        }
    }
    __syncthreads();
    #pragma unroll
    for (int i = 0; i < 2; i++) {
        int idx = tid + i*1024;
        if (idx < NA) g_off[b*NA + idx] = s[idx];
    }
}

__global__ void k_fill(const int* __restrict__ nbidx, const float* __restrict__ nbdist) {
    int e = blockIdx.x * blockDim.x + threadIdx.x;
    if (e >= BB*EE) return;
    int b = e / EE;
    int i = nbidx[e*2 + 0];
    int j = nbidx[e*2 + 1];
    float d = nbdist[e];
    float v  = erfcf(d * 0.70710678118f) / d;
    float fc = (d < 5.0f) ? 0.5f*(__cosf(PI_F * d * 0.2f) + 1.0f) : 0.0f;
    float vsr = v - fc / d;
    int pos = g_off[b*NA + i] + atomicAdd(&g_fil[b*NA + i], 1);
    g_elj[b*EE + pos] = j;
    g_elv[b*EE + pos] = vsr;
}

__global__ void k_gather() {
    int bn = blockIdx.x;
    int b  = bn / NA;
    int tid = threadIdx.x;
    int start = g_off[bn];
    int cnt   = g_cnt[bn];
    const int*   ej = g_elj + b*EE + start;
    const float* ev = g_elv + b*EE + start;
    const float* qb = g_q + (size_t)b*NA*DD;
    float acc = 0.f;
    int e = 0;
    for (; e + 2 <= cnt; e += 2) {
        int   j0 = ej[e],   j1 = ej[e+1];
        float v0 = ev[e],   v1 = ev[e+1];
        acc += v0 * qb[(size_t)j0*DD + tid];
        acc += v1 * qb[(size_t)j1*DD + tid];
    }
    if (e < cnt) acc += ev[e] * qb[(size_t)ej[e]*DD + tid];
    g_pot[(size_t)bn*DD + tid] = acc;
}

/* ---------------- fp16 TN fused: Sc = G*(c^T q), Ss = G*(s^T q) ------------ */
/* grid (18, 2, 8), 256 threads, 8 warps 4m x 2n. tile 128m x 128n, kt 16. */
__global__ void __launch_bounds__(256, 1) k_sf() {
    __shared__ __align__(16) half sc[16][136];   /* [atom-k][kvec-m] */
    __shared__ __align__(16) half ss[16][136];
    __shared__ __align__(16) half sq[16][136];   /* [atom-k][chan-n] */
    int b  = blockIdx.z;
    int m0 = blockIdx.x * 128;
    int n0 = blockIdx.y * 128;
    int tid = threadIdx.x, warp = tid >> 5, lane = tid & 31;
    int wm = warp & 3, wn = warp >> 2;
    int tg = lane & 3, gp = lane >> 2;
    const half* cosb = g_cosh + (size_t)b * NA * KP;
    const half* sinb = g_sinh + (size_t)b * NA * KP;
    const half* qb   = g_qh   + (size_t)b * NA * DD;
    float accC[2][8][4] = {}, accS[2][8][4] = {};
    int lrow = tid >> 4, lc8 = (tid & 15) * 8;
    /* A (trans from [k][m]) fragment addrs, 2 m-frags per warp */
    int arow = (lane & 7) + ((lane >> 4) << 3);
    unsigned aAc[2], aAs[2], aBq[4];
    #pragma unroll
    for (int f = 0; f < 2; f++) {
        int acol = wm*32 + f*16 + ((lane >> 3) & 1) * 8;
        aAc[f] = sptr(&sc[arow][acol]);
        aAs[f] = sptr(&ss[arow][acol]);
    }
    int brow = lane & 15, bc8 = ((lane >> 4) << 3);
    #pragma unroll
    for (int p = 0; p < 4; p++) aBq[p] = sptr(&sq[brow][wn*64 + p*16 + bc8]);
    const half* pc = cosb + (size_t)lrow*KP + m0 + lc8;
    const half* ps = sinb + (size_t)lrow*KP + m0 + lc8;
    const half* pq = qb   + (size_t)lrow*DD + n0 + lc8;
    uint4 vc = *(const uint4*)pc, vs = *(const uint4*)ps, vq = *(const uint4*)pq;
    for (int nt = 0; nt < NA; nt += 16) {
        *(uint4*)&sc[lrow][lc8] = vc;
        *(uint4*)&ss[lrow][lc8] = vs;
        *(uint4*)&sq[lrow][lc8] = vq;
        __syncthreads();
        if (nt + 16 < NA) {
            pc += 16*KP; ps += 16*KP; pq += 16*DD;
            vc = *(const uint4*)pc; vs = *(const uint4*)ps; vq = *(const uint4*)pq;
        }
        unsigned af[2][4], sf_[2][4];
        ldsm4t(af[0],  aAc[0]); ldsm4t(af[1],  aAc[1]);
        ldsm4t(sf_[0], aAs[0]); ldsm4t(sf_[1], aAs[1]);
        #pragma unroll
        for (int p = 0; p < 4; p++) {
            unsigned bq[4]; ldsm4t(bq, aBq[p]);
            #pragma unroll
            for (int f = 0; f < 2; f++) {
                mma16816(accC[f][2*p  ], af[f],  bq[0], bq[1]);
                mma16816(accC[f][2*p+1], af[f],  bq[2], bq[3]);
                mma16816(accS[f][2*p  ], sf_[f], bq[0], bq[1]);
                mma16816(accS[f][2*p+1], sf_[f], bq[2], bq[3]);
            }
        }
        __syncthreads();
    }
    #pragma unroll
    for (int f = 0; f < 2; f++) {
        int gm0 = m0 + wm*32 + f*16 + gp, gm1 = gm0 + 8;
        float G0 = g_G[b*KP + gm0], G1 = g_G[b*KP + gm1];
        #pragma unroll
        for (int nf = 0; nf < 8; nf++) {
            int gn = n0 + wn*64 + nf*8 + tg*2;
            *(half2*)&g_Sch[(size_t)(b*KP+gm0)*DD + gn] = __floats2half2_rn(G0*accC[f][nf][0], G0*accC[f][nf][1]);
            *(half2*)&g_Sch[(size_t)(b*KP+gm1)*DD + gn] = __floats2half2_rn(G1*accC[f][nf][2], G1*accC[f][nf][3]);
            *(half2*)&g_Ssh[(size_t)(b*KP+gm0)*DD + gn] = __floats2half2_rn(G0*accS[f][nf][0], G0*accS[f][nf][1]);
            *(half2*)&g_Ssh[(size_t)(b*KP+gm1)*DD + gn] = __floats2half2_rn(G1*accS[f][nf][2], G1*accS[f][nf][3]);
        }
    }
}

/* ---------------- fp16 NN fused: pot += c@Sc + s@Ss ------------------------ */
/* grid (16, 2, 8), 256 threads, 8 warps 4m x 2n. tile 128m x 128n, kt 16. */
__global__ void __launch_bounds__(256, 1) k_pot() {
    __shared__ __align__(16) half sAc[128][24];  /* [atom-m][kvec-k] */
    __shared__ __align__(16) half sAs[128][24];
    __shared__ __align__(16) half sBc[16][136];  /* [kvec-k][chan-n] */
    __shared__ __align__(16) half sBs[16][136];
    int b  = blockIdx.z;
    int m0 = blockIdx.x * 128;
    int n0 = blockIdx.y * 128;
    int tid = threadIdx.x, warp = tid >> 5, lane = tid & 31;
    int wm = warp & 3, wn = warp >> 2;
    int tg = lane & 3, gp = lane >> 2;
    const half* cosb = g_cosh + (size_t)b * NA * KP;
    const half* sinb = g_sinh + (size_t)b * NA * KP;
    float acc[2][8][4] = {};
    int rowA = tid >> 1, cA8 = (tid & 1) * 8;
    bool okA = (m0 + rowA) < NA;
    int rowB = tid >> 4, cB8 = (tid & 15) * 8;
    /* A (no trans, [m][k]) fragment addrs */
    int r = lane & 7, g = lane >> 3;
    unsigned aA[2], aS[2], aBc[4], aBs[4];
    #pragma unroll
    for (int f = 0; f < 2; f++) {
        int rr = wm*32 + f*16 + r + (g & 1)*8;
        int cc = (g >> 1) * 8;
        aA[f] = sptr(&sAc[rr][cc]);
        aS[f] = sptr(&sAs[rr][cc]);
    }
    int brow = lane & 15, bc8 = ((lane >> 4) << 3);
    #pragma unroll
    for (int p = 0; p < 4; p++) {
        aBc[p] = sptr(&sBc[brow][wn*64 + p*16 + bc8]);
        aBs[p] = sptr(&sBs[brow][wn*64 + p*16 + bc8]);
    }
    const half* pAc = cosb + (size_t)(m0 + rowA)*KP + cA8;
    const half* pAs = sinb + (size_t)(m0 + rowA)*KP + cA8;
    const half* pBc = g_Sch + (size_t)((size_t)b*KP + rowB)*DD + n0 + cB8;
    const half* pBs = g_Ssh + (size_t)((size_t)b*KP + rowB)*DD + n0 + cB8;
    const uint4 z4 = make_uint4(0,0,0,0);
    uint4 vAc = okA ? *(const uint4*)pAc : z4;
    uint4 vAs = okA ? *(const uint4*)pAs : z4;
    uint4 vBc = *(const uint4*)pBc;
    uint4 vBs = *(const uint4*)pBs;
    for (int kt = 0; kt < KP; kt += 16) {
        *(uint4*)&sAc[rowA][cA8] = vAc;
        *(uint4*)&sAs[rowA][cA8] = vAs;
        *(uint4*)&sBc[rowB][cB8] = vBc;
        *(uint4*)&sBs[rowB][cB8] = vBs;
        __syncthreads();
        if (kt + 16 < KP) {
            pAc += 16; pAs += 16; pBc += 16*DD; pBs += 16*DD;
            vAc = okA ? *(const uint4*)pAc : z4;
            vAs = okA ? *(const uint4*)pAs : z4;
            vBc = *(const uint4*)pBc;
            vBs = *(const uint4*)pBs;
        }
        unsigned af[2][4], sf_[2][4];
        ldsm4(af[0],  aA[0]); ldsm4(af[1],  aA[1]);
        ldsm4(sf_[0], aS[0]); ldsm4(sf_[1], aS[1]);
        #pragma unroll
        for (int p = 0; p < 4; p++) {
            unsigned bb[4];
            ldsm4t(bb, aBc[p]);
            #pragma unroll
            for (int f = 0; f < 2; f++) {
                mma16816(acc[f][2*p  ], af[f], bb[0], bb[1]);
                mma16816(acc[f][2*p+1], af[f], bb[2], bb[3]);
            }
            ldsm4t(bb, aBs[p]);
            #pragma unroll
            for (int f = 0; f < 2; f++) {
                mma16816(acc[f][2*p  ], sf_[f], bb[0], bb[1]);
                mma16816(acc[f][2*p+1], sf_[f], bb[2], bb[3]);
            }
        }
        __syncthreads();
    }
    #pragma unroll
    for (int f = 0; f < 2; f++) {
        int gm0 = m0 + wm*32 + f*16 + gp, gm1 = gm0 + 8;
        #pragma unroll
        for (int nf = 0; nf < 8; nf++) {
            int gn = n0 + wn*64 + nf*8 + tg*2;
            if (gm0 < NA) {
                float2* p = (float2*)&g_pot[(size_t)(b*NA+gm0)*DD + gn];
                float2 v = *p; v.x += acc[f][nf][0]; v.y += acc[f][nf][1]; *p = v;
            }
            if (gm1 < NA) {
                float2* p = (float2*)&g_pot[(size_t)(b*NA+gm1)*DD + gn];
                float2 v = *p; v.x += acc[f][nf][2]; v.y += acc[f][nf][3]; *p = v;
            }
        }
    }
}

/* ---------------- out = (pot + self*q) * q -------------------------------- */
__global__ void k_final(float* __restrict__ out) {
    int idx = blockIdx.x * blockDim.x + threadIdx.x;
    float qv = g_q[idx];
    out[idx] = (g_pot[idx] + C_SELF * qv) * qv;
}

/* ---------------- launch -------------------------------------------------- */
extern "C" void kernel_launch(void* const* d_in, const int* in_sizes, int n_in,
                              void* d_out, int out_size) {
    const float* features = (const float*)d_in[0];
    const float* positions= (const float*)d_in[1];
    const float* cell     = (const float*)d_in[2];
    const int*   nbidx    = (const int*)  d_in[3];
    const float* nbdist   = (const float*)d_in[4];
    const float* W        = (const float*)d_in[5];
    const float* bias     = (const float*)d_in[6];
    float* out = (float*)d_out;

    k_kG     <<<dim3((KP+255)/256, BB), 256>>>(cell);
    k_charges<<<dim3((BB*NA)/64, DD/64), 128>>>(features, W, bias);
    k_phase  <<<BB*NA, 256>>>(positions, cell);
    k_init0  <<<(2*BB*NA+255)/256, 256>>>();
    k_count  <<<(BB*EE+255)/256, 256>>>(nbidx);
    k_scan   <<<BB, 1024>>>();
    k_fill   <<<(BB*EE+255)/256, 256>>>(nbidx, nbdist);
    k_gather <<<BB*NA, 256>>>();
    k_sf     <<<dim3(KP/128, DD/128, BB), 256>>>();
    k_pot    <<<dim3((NA+127)/128, DD/128, BB), 256>>>();
    k_final  <<<(BB*NA*DD)/256, 256>>>(out);
    (void)in_sizes; (void)n_in; (void)out_size;
}

// round 5
// speedup vs baseline: 7.7948x; 1.6473x over previous
#include <cuda_runtime.h>
#include <cuda_fp16.h>
#include <math.h>

#define BB 8
#define NA 2000
#define DD 256
#define EE 64000
#define KNUMH 1098       /* half-space k-vectors (m = 0..1097) */
#define KP 1152          /* 128 * 9, padded with G=0, cos/sin=0 */
#define PI_F 3.14159265358979f
#define C_SELF (-0.7978845608028654f)   /* -sqrt(2/pi)/sigma */

/* ---------------- scratch (device globals; no allocations allowed) -------- */
__device__ float g_q  [BB*NA*DD];
__device__ float g_pot[BB*NA*DD];
__device__ __align__(16) half g_qh  [BB*NA*DD];
__device__ __align__(16) half g_cosh[(size_t)BB*NA*KP];
__device__ __align__(16) half g_sinh[(size_t)BB*NA*KP];
__device__ __align__(16) half g_Sch [BB*KP*DD];
__device__ __align__(16) half g_Ssh [BB*KP*DD];
__device__ float g_G  [BB*KP];
__device__ int   g_cnt[BB*NA];
__device__ int   g_off[BB*NA];
__device__ int   g_fil[BB*NA];
__device__ int   g_elj[BB*EE];
__device__ float g_elv[BB*EE];

/* ---------------- MMA / ldmatrix helpers ----------------------------------- */
__device__ __forceinline__ unsigned sptr(const void* p) {
    return (unsigned)__cvta_generic_to_shared(p);
}
__device__ __forceinline__ void ldsm4(unsigned* r, unsigned a) {
    asm volatile("ldmatrix.sync.aligned.m8n8.x4.shared.b16 {%0,%1,%2,%3},[%4];"
        : "=r"(r[0]), "=r"(r[1]), "=r"(r[2]), "=r"(r[3]) : "r"(a));
}
__device__ __forceinline__ void ldsm4t(unsigned* r, unsigned a) {
    asm volatile("ldmatrix.sync.aligned.m8n8.x4.trans.shared.b16 {%0,%1,%2,%3},[%4];"
        : "=r"(r[0]), "=r"(r[1]), "=r"(r[2]), "=r"(r[3]) : "r"(a));
}
__device__ __forceinline__ void mma16816(float* d, const unsigned* a,
                                         unsigned b0, unsigned b1) {
    asm volatile(
        "mma.sync.aligned.m16n8k16.row.col.f32.f16.f16.f32 "
        "{%0,%1,%2,%3},{%4,%5,%6,%7},{%8,%9},{%0,%1,%2,%3};"
        : "+f"(d[0]), "+f"(d[1]), "+f"(d[2]), "+f"(d[3])
        : "r"(a[0]), "r"(a[1]), "r"(a[2]), "r"(a[3]), "r"(b0), "r"(b1));
}
__device__ __forceinline__ unsigned f2tf(float x) {
    unsigned r; asm("cvt.rna.tf32.f32 %0, %1;" : "=r"(r) : "f"(x)); return r;
}
__device__ __forceinline__ void mma_tf32(float* d, unsigned a0, unsigned a1,
                                         unsigned a2, unsigned a3,
                                         unsigned b0, unsigned b1) {
    asm volatile(
        "mma.sync.aligned.m16n8k8.row.col.f32.tf32.tf32.f32 "
        "{%0,%1,%2,%3},{%4,%5,%6,%7},{%8,%9},{%0,%1,%2,%3};"
        : "+f"(d[0]), "+f"(d[1]), "+f"(d[2]), "+f"(d[3])
        : "r"(a0), "r"(a1), "r"(a2), "r"(a3), "r"(b0), "r"(b1));
}

/* ---------------- Green's function (half-space, x2 folded in) -------------- */
__global__ void k_kG(const float* __restrict__ cell) {
    int k = blockIdx.x * blockDim.x + threadIdx.x;
    int b = blockIdx.y;
    if (k >= KP) return;
    const float* C = cell + b * 9;
    float c00=C[0],c01=C[1],c02=C[2];
    float c10=C[3],c11=C[4],c12=C[5];
    float c20=C[6],c21=C[7],c22=C[8];
    float det = c00*(c11*c22-c12*c21) - c01*(c10*c22-c12*c20) + c02*(c10*c21-c11*c20);
    float id = 1.0f/det;
    float i00=(c11*c22-c12*c21)*id, i01=(c02*c21-c01*c22)*id, i02=(c01*c12-c02*c11)*id;
    float i10=(c12*c20-c10*c22)*id, i11=(c00*c22-c02*c20)*id, i12=(c02*c10-c00*c12)*id;
    float i20=(c10*c21-c11*c20)*id, i21=(c01*c20-c00*c21)*id, i22=(c00*c11-c01*c10)*id;
    float G = 0.f;
    if (k < KNUMH) {
        int m = k;                              /* half-space: m in [0,1098) */
        float ni = (float)(m/169 - 6);
        float nj = (float)((m/13)%13 - 6);
        float nk = (float)(m%13 - 6);
        float kx = 2.0f*PI_F*(i00*ni + i01*nj + i02*nk);
        float ky = 2.0f*PI_F*(i10*ni + i11*nj + i12*nk);
        float kz = 2.0f*PI_F*(i20*ni + i21*nj + i22*nk);
        float k2 = kx*kx + ky*ky + kz*kz;
        /* 8π = 2 * 4π : ±k pair contributes twice the half-space term */
        G = 8.0f*PI_F/fabsf(det) * __expf(-0.5f*k2) / k2;   /* sigma = 1 */
    }
    g_G[b*KP + k] = G;
}

/* ---------------- charges = features @ W^T + b (tf32 MMA) ------------------ */
__global__ void k_charges(const float* __restrict__ A, const float* __restrict__ Wm,
                          const float* __restrict__ bias) {
    __shared__ unsigned sA[64][20];   /* [m][k] tf32 */
    __shared__ unsigned sB[16][72];   /* [k][n] tf32 */
    int m0 = blockIdx.x * 64, n0 = blockIdx.y * 64;
    int tid = threadIdx.x, warp = tid >> 5, lane = tid & 31;
    int tg = lane & 3, gp = lane >> 2;
    int mb = warp * 16;
    float acc[8][4] = {};
    for (int kt = 0; kt < 256; kt += 16) {
        #pragma unroll
        for (int i = 0; i < 2; i++) {
            int t = tid + i*128;
            int row = t >> 2, k4 = (t & 3) * 4;
            float4 v = *(const float4*)&A[(size_t)(m0+row)*256 + kt + k4];
            sA[row][k4+0]=f2tf(v.x); sA[row][k4+1]=f2tf(v.y);
            sA[row][k4+2]=f2tf(v.z); sA[row][k4+3]=f2tf(v.w);
            float4 w = *(const float4*)&Wm[(size_t)(n0+row)*256 + kt + k4];
            sB[k4+0][row]=f2tf(w.x); sB[k4+1][row]=f2tf(w.y);
            sB[k4+2][row]=f2tf(w.z); sB[k4+3][row]=f2tf(w.w);
        }
        __syncthreads();
        #pragma unroll
        for (int k0 = 0; k0 < 16; k0 += 8) {
            unsigned a0 = sA[mb+gp  ][k0+tg],   a1 = sA[mb+8+gp][k0+tg];
            unsigned a2 = sA[mb+gp  ][k0+tg+4], a3 = sA[mb+8+gp][k0+tg+4];
            #pragma unroll
            for (int n8 = 0; n8 < 8; n8++) {
                unsigned b0 = sB[k0+tg  ][n8*8+gp];
                unsigned b1 = sB[k0+tg+4][n8*8+gp];
                mma_tf32(acc[n8], a0, a1, a2, a3, b0, b1);
            }
        }
        __syncthreads();
    }
    int gm0 = m0 + mb + gp, gm1 = gm0 + 8;
    #pragma unroll
    for (int n8 = 0; n8 < 8; n8++) {
        int gn = n0 + n8*8 + tg*2;
        float b0 = bias[gn], b1 = bias[gn+1];
        float v0 = acc[n8][0] + b0, v1 = acc[n8][1] + b1;
        float v2 = acc[n8][2] + b0, v3 = acc[n8][3] + b1;
        *(float2*)&g_q[(size_t)gm0*DD + gn] = make_float2(v0, v1);
        *(float2*)&g_q[(size_t)gm1*DD + gn] = make_float2(v2, v3);
        *(half2*)&g_qh[(size_t)gm0*DD + gn] = __floats2half2_rn(v0, v1);
        *(half2*)&g_qh[(size_t)gm1*DD + gn] = __floats2half2_rn(v2, v3);
    }
}

/* ---------------- phases via separable axis factors (half-space) ----------- */
__global__ void k_phase(const float* __restrict__ pos, const float* __restrict__ cell) {
    __shared__ float er[3][13], ei[3][13];
    int bn = blockIdx.x;
    int b  = bn / NA;
    int tid = threadIdx.x;
    float px = pos[bn*3+0], py = pos[bn*3+1], pz = pos[bn*3+2];
    if (tid < 39) {
        const float* C = cell + b * 9;
        float c00=C[0],c01=C[1],c02=C[2];
        float c10=C[3],c11=C[4],c12=C[5];
        float c20=C[6],c21=C[7],c22=C[8];
        float det = c00*(c11*c22-c12*c21) - c01*(c10*c22-c12*c20) + c02*(c10*c21-c11*c20);
        float id = 1.0f/det;
        float i00=(c11*c22-c12*c21)*id, i01=(c02*c21-c01*c22)*id, i02=(c01*c12-c02*c11)*id;
        float i10=(c12*c20-c10*c22)*id, i11=(c00*c22-c02*c20)*id, i12=(c02*c10-c00*c12)*id;
        float i20=(c10*c21-c11*c20)*id, i21=(c01*c20-c00*c21)*id, i22=(c00*c11-c01*c10)*id;
        int axis = tid / 13, idx = tid % 13;
        float u;                               /* 2π * (column axis of inv) . p */
        if      (axis == 0) u = i00*px + i10*py + i20*pz;
        else if (axis == 1) u = i01*px + i11*py + i21*pz;
        else                u = i02*px + i12*py + i22*pz;
        float ph = 2.0f*PI_F * u * (float)(idx - 6);
        float s, c; __sincosf(ph, &s, &c);
        er[axis][idx] = c; ei[axis][idx] = s;
    }
    __syncthreads();
    size_t base = (size_t)bn * KP;
    for (int k2 = tid; k2 < KP/2; k2 += 256) {
        int k = k2 * 2;
        float c0=0.f, s0=0.f, c1=0.f, s1=0.f;
        #pragma unroll
        for (int h = 0; h < 2; h++) {
            int m = k + h;                      /* half-space index, no skip */
            if (m < KNUMH) {
                int i = m / 169; int r = m - i*169;
                int j = r / 13;  int l = r - j*13;
                float ar = er[0][i], ai = ei[0][i];
                float br = er[1][j], bi = ei[1][j];
                float tr = ar*br - ai*bi, ti = ar*bi + ai*br;
                float cr = er[2][l], ci = ei[2][l];
                float cc = tr*cr - ti*ci, ss = tr*ci + ti*cr;
                if (h == 0) { c0 = cc; s0 = ss; } else { c1 = cc; s1 = ss; }
            }
        }
        *(half2*)&g_cosh[base + k] = __floats2half2_rn(c0, c1);
        *(half2*)&g_sinh[base + k] = __floats2half2_rn(s0, s1);
    }
}

/* ---------------- edge pipeline: count -> scan -> fill -> gather ----------- */
__global__ void k_init0() {
    int idx = blockIdx.x * blockDim.x + threadIdx.x;
    if (idx < BB*NA) g_cnt[idx] = 0;
    else             g_fil[idx - BB*NA] = 0;
}

__global__ void k_count(const int* __restrict__ nbidx) {
    int e = blockIdx.x * blockDim.x + threadIdx.x;
    if (e >= BB*EE) return;
    int b = e / EE;
    int i = nbidx[e*2];
    atomicAdd(&g_cnt[b*NA + i], 1);
}

__global__ void k_scan() {
    __shared__ int s[2048];
    int b = blockIdx.x, tid = threadIdx.x;
    #pragma unroll
    for (int i = 0; i < 2; i++) {
        int idx = tid + i*1024;
        s[idx] = (idx < NA) ? g_cnt[b*NA + idx] : 0;
    }
    int offset = 1;
    for (int d = 1024; d > 0; d >>= 1) {
        __syncthreads();
        if (tid < d) {
            int ai = offset*(2*tid+1) - 1;
            int bi = offset*(2*tid+2) - 1;
            s[bi] += s[ai];
        }
        offset <<= 1;
    }
    if (tid == 0) s[2047] = 0;
    for (int d = 1; d < 2048; d <<= 1) {
        offset >>= 1;
        __syncthreads();
        if (tid < d) {
            int ai = offset*(2*tid+1) - 1;
            int bi = offset*(2*tid+2) - 1;
            int t = s[ai]; s[ai] = s[bi]; s[bi] += t;
        }
    }
    __syncthreads();
    #pragma unroll
    for (int i = 0; i < 2; i++) {
        int idx = tid + i*1024;
        if (idx < NA) g_off[b*NA + idx] = s[idx];
    }
}

__global__ void k_fill(const int* __restrict__ nbidx, const float* __restrict__ nbdist) {
    int e = blockIdx.x * blockDim.x + threadIdx.x;
    if (e >= BB*EE) return;
    int b = e / EE;
    int i = nbidx[e*2 + 0];
    int j = nbidx[e*2 + 1];
    float d = nbdist[e];
    float v  = erfcf(d * 0.70710678118f) / d;
    float fc = (d < 5.0f) ? 0.5f*(__cosf(PI_F * d * 0.2f) + 1.0f) : 0.0f;
    float vsr = v - fc / d;
    int pos = g_off[b*NA + i] + atomicAdd(&g_fil[b*NA + i], 1);
    g_elj[b*EE + pos] = j;
    g_elv[b*EE + pos] = vsr;
}

__global__ void k_gather() {
    int bn = blockIdx.x;
    int b  = bn / NA;
    int tid = threadIdx.x;
    int start = g_off[bn];
    int cnt   = g_cnt[bn];
    const int*   ej = g_elj + b*EE + start;
    const float* ev = g_elv + b*EE + start;
    const float* qb = g_q + (size_t)b*NA*DD;
    float acc = 0.f;
    int e = 0;
    for (; e + 2 <= cnt; e += 2) {
        int   j0 = ej[e],   j1 = ej[e+1];
        float v0 = ev[e],   v1 = ev[e+1];
        acc += v0 * qb[(size_t)j0*DD + tid];
        acc += v1 * qb[(size_t)j1*DD + tid];
    }
    if (e < cnt) acc += ev[e] * qb[(size_t)ej[e]*DD + tid];
    g_pot[(size_t)bn*DD + tid] = acc;
}

/* ---------------- fp16 TN fused: Sc = G*(c^T q), Ss = G*(s^T q) ------------ */
/* grid (9, 2, 8), 256 threads, 8 warps 4m x 2n. tile 128m x 128n, kt 16. */
__global__ void __launch_bounds__(256, 1) k_sf() {
    __shared__ __align__(16) half sc[16][136];   /* [atom-k][kvec-m] */
    __shared__ __align__(16) half ss[16][136];
    __shared__ __align__(16) half sq[16][136];   /* [atom-k][chan-n] */
    int b  = blockIdx.z;
    int m0 = blockIdx.x * 128;
    int n0 = blockIdx.y * 128;
    int tid = threadIdx.x, warp = tid >> 5, lane = tid & 31;
    int wm = warp & 3, wn = warp >> 2;
    int tg = lane & 3, gp = lane >> 2;
    const half* cosb = g_cosh + (size_t)b * NA * KP;
    const half* sinb = g_sinh + (size_t)b * NA * KP;
    const half* qb   = g_qh   + (size_t)b * NA * DD;
    float accC[2][8][4] = {}, accS[2][8][4] = {};
    int lrow = tid >> 4, lc8 = (tid & 15) * 8;
    int arow = (lane & 7) + ((lane >> 4) << 3);
    unsigned aAc[2], aAs[2], aBq[4];
    #pragma unroll
    for (int f = 0; f < 2; f++) {
        int acol = wm*32 + f*16 + ((lane >> 3) & 1) * 8;
        aAc[f] = sptr(&sc[arow][acol]);
        aAs[f] = sptr(&ss[arow][acol]);
    }
    int brow = lane & 15, bc8 = ((lane >> 4) << 3);
    #pragma unroll
    for (int p = 0; p < 4; p++) aBq[p] = sptr(&sq[brow][wn*64 + p*16 + bc8]);
    const half* pc = cosb + (size_t)lrow*KP + m0 + lc8;
    const half* ps = sinb + (size_t)lrow*KP + m0 + lc8;
    const half* pq = qb   + (size_t)lrow*DD + n0 + lc8;
    uint4 vc = *(const uint4*)pc, vs = *(const uint4*)ps, vq = *(const uint4*)pq;
    for (int nt = 0; nt < NA; nt += 16) {
        *(uint4*)&sc[lrow][lc8] = vc;
        *(uint4*)&ss[lrow][lc8] = vs;
        *(uint4*)&sq[lrow][lc8] = vq;
        __syncthreads();
        if (nt + 16 < NA) {
            pc += 16*KP; ps += 16*KP; pq += 16*DD;
            vc = *(const uint4*)pc; vs = *(const uint4*)ps; vq = *(const uint4*)pq;
        }
        unsigned af[2][4], sf_[2][4];
        ldsm4t(af[0],  aAc[0]); ldsm4t(af[1],  aAc[1]);
        ldsm4t(sf_[0], aAs[0]); ldsm4t(sf_[1], aAs[1]);
        #pragma unroll
        for (int p = 0; p < 4; p++) {
            unsigned bq[4]; ldsm4t(bq, aBq[p]);
            #pragma unroll
            for (int f = 0; f < 2; f++) {
                mma16816(accC[f][2*p  ], af[f],  bq[0], bq[1]);
                mma16816(accC[f][2*p+1], af[f],  bq[2], bq[3]);
                mma16816(accS[f][2*p  ], sf_[f], bq[0], bq[1]);
                mma16816(accS[f][2*p+1], sf_[f], bq[2], bq[3]);
            }
        }
        __syncthreads();
    }
    #pragma unroll
    for (int f = 0; f < 2; f++) {
        int gm0 = m0 + wm*32 + f*16 + gp, gm1 = gm0 + 8;
        float G0 = g_G[b*KP + gm0], G1 = g_G[b*KP + gm1];
        #pragma unroll
        for (int nf = 0; nf < 8; nf++) {
            int gn = n0 + wn*64 + nf*8 + tg*2;
            *(half2*)&g_Sch[(size_t)(b*KP+gm0)*DD + gn] = __floats2half2_rn(G0*accC[f][nf][0], G0*accC[f][nf][1]);
            *(half2*)&g_Sch[(size_t)(b*KP+gm1)*DD + gn] = __floats2half2_rn(G1*accC[f][nf][2], G1*accC[f][nf][3]);
            *(half2*)&g_Ssh[(size_t)(b*KP+gm0)*DD + gn] = __floats2half2_rn(G0*accS[f][nf][0], G0*accS[f][nf][1]);
            *(half2*)&g_Ssh[(size_t)(b*KP+gm1)*DD + gn] = __floats2half2_rn(G1*accS[f][nf][2], G1*accS[f][nf][3]);
        }
    }
}

/* ---------------- fp16 NN fused + epilogue: out = (pot+acc+Cq)q ------------ */
/* grid (16, 2, 8), 256 threads, 8 warps 4m x 2n. tile 128m x 128n, kt 16. */
__global__ void __launch_bounds__(256, 1) k_pot(float* __restrict__ out) {
    __shared__ __align__(16) half sAc[128][24];  /* [atom-m][kvec-k] */
    __shared__ __align__(16) half sAs[128][24];
    __shared__ __align__(16) half sBc[16][136];  /* [kvec-k][chan-n] */
    __shared__ __align__(16) half sBs[16][136];
    int b  = blockIdx.z;
    int m0 = blockIdx.x * 128;
    int n0 = blockIdx.y * 128;
    int tid = threadIdx.x, warp = tid >> 5, lane = tid & 31;
    int wm = warp & 3, wn = warp >> 2;
    int tg = lane & 3, gp = lane >> 2;
    const half* cosb = g_cosh + (size_t)b * NA * KP;
    const half* sinb = g_sinh + (size_t)b * NA * KP;
    float acc[2][8][4] = {};
    int rowA = tid >> 1, cA8 = (tid & 1) * 8;
    bool okA = (m0 + rowA) < NA;
    int rowB = tid >> 4, cB8 = (tid & 15) * 8;
    int r = lane & 7, g = lane >> 3;
    unsigned aA[2], aS[2], aBc[4], aBs[4];
    #pragma unroll
    for (int f = 0; f < 2; f++) {
        int rr = wm*32 + f*16 + r + (g & 1)*8;
        int cc = (g >> 1) * 8;
        aA[f] = sptr(&sAc[rr][cc]);
        aS[f] = sptr(&sAs[rr][cc]);
    }
    int brow = lane & 15, bc8 = ((lane >> 4) << 3);
    #pragma unroll
    for (int p = 0; p < 4; p++) {
        aBc[p] = sptr(&sBc[brow][wn*64 + p*16 + bc8]);
        aBs[p] = sptr(&sBs[brow][wn*64 + p*16 + bc8]);
    }
    const half* pAc = cosb + (size_t)(m0 + rowA)*KP + cA8;
    const half* pAs = sinb + (size_t)(m0 + rowA)*KP + cA8;
    const half* pBc = g_Sch + (size_t)((size_t)b*KP + rowB)*DD + n0 + cB8;
    const half* pBs = g_Ssh + (size_t)((size_t)b*KP + rowB)*DD + n0 + cB8;
    const uint4 z4 = make_uint4(0,0,0,0);
    uint4 vAc = okA ? *(const uint4*)pAc : z4;
    uint4 vAs = okA ? *(const uint4*)pAs : z4;
    uint4 vBc = *(const uint4*)pBc;
    uint4 vBs = *(const uint4*)pBs;
    for (int kt = 0; kt < KP; kt += 16) {   /* 72 iterations */
        *(uint4*)&sAc[rowA][cA8] = vAc;
        *(uint4*)&sAs[rowA][cA8] = vAs;
        *(uint4*)&sBc[rowB][cB8] = vBc;
        *(uint4*)&sBs[rowB][cB8] = vBs;
        __syncthreads();
        if (kt + 16 < KP) {
            pAc += 16; pAs += 16; pBc += 16*DD; pBs += 16*DD;
            vAc = okA ? *(const uint4*)pAc : z4;
            vAs = okA ? *(const uint4*)pAs : z4;
            vBc = *(const uint4*)pBc;
            vBs = *(const uint4*)pBs;
        }
        unsigned af[2][4], sf_[2][4];
        ldsm4(af[0],  aA[0]); ldsm4(af[1],  aA[1]);
        ldsm4(sf_[0], aS[0]); ldsm4(sf_[1], aS[1]);
        #pragma unroll
        for (int p = 0; p < 4; p++) {
            unsigned bb[4];
            ldsm4t(bb, aBc[p]);
            #pragma unroll
            for (int f = 0; f < 2; f++) {
                mma16816(acc[f][2*p  ], af[f], bb[0], bb[1]);
                mma16816(acc[f][2*p+1], af[f], bb[2], bb[3]);
            }
            ldsm4t(bb, aBs[p]);
            #pragma unroll
            for (int f = 0; f < 2; f++) {
                mma16816(acc[f][2*p  ], sf_[f], bb[0], bb[1]);
                mma16816(acc[f][2*p+1], sf_[f], bb[2], bb[3]);
            }
        }
        __syncthreads();
    }
    /* epilogue: out = (pot_real + acc + C_SELF*q) * q */
    #pragma unroll
    for (int f = 0; f < 2; f++) {
        int gm0 = m0 + wm*32 + f*16 + gp, gm1 = gm0 + 8;
        #pragma unroll
        for (int nf = 0; nf < 8; nf++) {
            int gn = n0 + wn*64 + nf*8 + tg*2;
            if (gm0 < NA) {
                size_t idx = (size_t)(b*NA+gm0)*DD + gn;
                float2 pr = *(const float2*)&g_pot[idx];
                float2 qv = *(const float2*)&g_q[idx];
                float2 o;
                o.x = (pr.x + acc[f][nf][0] + C_SELF*qv.x) * qv.x;
                o.y = (pr.y + acc[f][nf][1] + C_SELF*qv.y) * qv.y;
                *(float2*)&out[idx] = o;
            }
            if (gm1 < NA) {
                size_t idx = (size_t)(b*NA+gm1)*DD + gn;
                float2 pr = *(const float2*)&g_pot[idx];
                float2 qv = *(const float2*)&g_q[idx];
                float2 o;
                o.x = (pr.x + acc[f][nf][2] + C_SELF*qv.x) * qv.x;
                o.y = (pr.y + acc[f][nf][3] + C_SELF*qv.y) * qv.y;
                *(float2*)&out[idx] = o;
            }
        }
    }
}

/* ---------------- launch -------------------------------------------------- */
extern "C" void kernel_launch(void* const* d_in, const int* in_sizes, int n_in,
                              void* d_out, int out_size) {
    const float* features = (const float*)d_in[0];
    const float* positions= (const float*)d_in[1];
    const float* cell     = (const float*)d_in[2];
    const int*   nbidx    = (const int*)  d_in[3];
    const float* nbdist   = (const float*)d_in[4];
    const float* W        = (const float*)d_in[5];
    const float* bias     = (const float*)d_in[6];
    float* out = (float*)d_out;

    k_kG     <<<dim3((KP+255)/256, BB), 256>>>(cell);
    k_charges<<<dim3((BB*NA)/64, DD/64), 128>>>(features, W, bias);
    k_phase  <<<BB*NA, 256>>>(positions, cell);
    k_init0  <<<(2*BB*NA+255)/256, 256>>>();
    k_count  <<<(BB*EE+255)/256, 256>>>(nbidx);
    k_scan   <<<BB, 1024>>>();
    k_fill   <<<(BB*EE+255)/256, 256>>>(nbidx, nbdist);
    k_gather <<<BB*NA, 256>>>();
    k_sf     <<<dim3(KP/128, DD/128, BB), 256>>>();
    k_pot    <<<dim3((NA+127)/128, DD/128, BB), 256>>>(out);
    (void)in_sizes; (void)n_in; (void)out_size;
}